// round 7
// baseline (speedup 1.0000x reference)
#include <cuda_runtime.h>
#include <cuda_bf16.h>
#include <cstddef>

#define NN 50000
#define EE 600000
#define GG 512
#define MM 2048
#define DD 128
#define FFN 256
#define LL 3
#define BN_EPS 1e-5f
#define SCAN_B 196   // ceil(NN/256)

// ---------------- scratch (device globals) ----------------
__device__ float g_bufA[NN * DD];   // layer output h
__device__ float g_bufB[NN * DD];   // hw branch
__device__ float g_bufR[NN * DD];   // residual branch
__device__ int   g_degin[NN];
__device__ int   g_degout[NN];
__device__ int   g_cursor[NN];
__device__ int   g_rowstart[NN + 1];
__device__ int   g_csr_src[EE];
__device__ int   g_bsum[SCAN_B];
__device__ int   g_boff[SCAN_B];
__device__ float g_norm_src[NN];
__device__ float g_norm_dst[NN];
__device__ float g_stats[2 * DD];
__device__ float g_cs[DD];
__device__ float g_cb[DD];
__device__ float g_gsum[GG * DD];
__device__ float g_gcnt[GG];
__device__ float g_msum[(MM + 1) * DD];
__device__ float g_mcnt[MM + 1];
__device__ float g_headin[(GG + MM) * DD];
__device__ float g_head1[(GG + MM) * FFN];
__device__ float g_head2[(GG + MM) * FFN];

// ---------------- f32x2 helpers ----------------
__device__ __forceinline__ unsigned long long pack_dup(float x) {
    unsigned long long p;
    unsigned int xb = __float_as_uint(x);
    asm("mov.b64 %0, {%1, %1};" : "=l"(p) : "r"(xb));
    return p;
}
__device__ __forceinline__ void ffma2(unsigned long long& acc, unsigned long long a,
                                      unsigned long long b) {
    asm("fma.rn.f32x2 %0, %1, %2, %0;" : "+l"(acc) : "l"(a), "l"(b));
}
__device__ __forceinline__ float2 unpack2(unsigned long long a) {
    float lo, hi;
    asm("mov.b64 {%0, %1}, %2;" : "=f"(lo), "=f"(hi) : "l"(a));
    return make_float2(lo, hi);
}

// ---------------- setup ----------------
__global__ void k_zero() {
    int i = blockIdx.x * blockDim.x + threadIdx.x;
    if (i < NN) { g_degin[i] = 0; g_degout[i] = 0; }
}

__global__ void k_hist(const int* __restrict__ src, const int* __restrict__ dst) {
    int e = blockIdx.x * blockDim.x + threadIdx.x;
    if (e < EE) {
        atomicAdd(&g_degout[src[e]], 1);
        atomicAdd(&g_degin[dst[e]], 1);
    }
}

__global__ void k_norms() {
    int i = blockIdx.x * blockDim.x + threadIdx.x;
    if (i < NN) {
        g_norm_src[i] = rsqrtf(fmaxf((float)g_degout[i], 1.0f));
        g_norm_dst[i] = rsqrtf(fmaxf((float)g_degin[i], 1.0f));
    }
    if (i < 2 * DD) g_stats[i] = 0.f;   // zero BN stats for layer 0
}

// ---------------- multi-block scan of g_degin -> g_rowstart ----------------
__global__ void k_scan1() {          // grid SCAN_B, block 256: block sums + zero cursor
    __shared__ int sh[256];
    int tid = threadIdx.x;
    int i = blockIdx.x * 256 + tid;
    int v = (i < NN) ? g_degin[i] : 0;
    if (i < NN) g_cursor[i] = 0;
    sh[tid] = v;
    __syncthreads();
    for (int off = 128; off > 0; off >>= 1) {
        if (tid < off) sh[tid] += sh[tid + off];
        __syncthreads();
    }
    if (tid == 0) g_bsum[blockIdx.x] = sh[0];
}

__global__ void k_scan2() {          // 1 block 256: exclusive scan of SCAN_B partials
    __shared__ int sh[256];
    int tid = threadIdx.x;
    int v = (tid < SCAN_B) ? g_bsum[tid] : 0;
    sh[tid] = v;
    __syncthreads();
    for (int off = 1; off < 256; off <<= 1) {
        int t = (tid >= off) ? sh[tid - off] : 0;
        __syncthreads();
        sh[tid] += t;
        __syncthreads();
    }
    if (tid < SCAN_B) g_boff[tid] = sh[tid] - v;
}

__global__ void k_scan3() {          // grid SCAN_B, block 256: local scan + offset
    __shared__ int sh[256];
    int tid = threadIdx.x;
    int i = blockIdx.x * 256 + tid;
    int v = (i < NN) ? g_degin[i] : 0;
    sh[tid] = v;
    __syncthreads();
    for (int off = 1; off < 256; off <<= 1) {
        int t = (tid >= off) ? sh[tid - off] : 0;
        __syncthreads();
        sh[tid] += t;
        __syncthreads();
    }
    if (i < NN) g_rowstart[i] = sh[tid] - v + g_boff[blockIdx.x];
    if (blockIdx.x == 0 && tid == 0) g_rowstart[NN] = EE;
}

__global__ void k_place(const int* __restrict__ src, const int* __restrict__ dst) {
    int e = blockIdx.x * blockDim.x + threadIdx.x;
    if (e < EE) {
        int d = dst[e];
        int slot = atomicAdd(&g_cursor[d], 1);
        g_csr_src[g_rowstart[d] + slot] = src[e];
    }
}

// ---------------- fused dual GEMM (fp32 FFMA2), 128x64 tile, 8 rows/thread ----------------
// Y1 = rs .* (Xn @ W1)      Xn = X*cs + cb (identity if cs==nullptr)
// Y2 = relu(Xn @ W2 + b2)
// Per thread: 8 rows x 4 cols x 2 matrices. LDS:FFMA2 = 16:128 per k-quad.
__global__ void __launch_bounds__(256, 1)
k_dualgemm(const float* __restrict__ X,
           const float* __restrict__ W1,
           const float* __restrict__ W2,
           const float* __restrict__ b2,
           const float* __restrict__ rs,
           const float* __restrict__ cs,
           const float* __restrict__ cb,
           float* __restrict__ Y1, float* __restrict__ Y2,
           int nrows) {
    extern __shared__ float sm[];
    float* Xs  = sm;               // 128*128 (64 KB)
    float* W1s = sm + 128 * 128;   // 128*64  (32 KB)
    float* W2s = W1s + 128 * 64;   // 128*64  (32 KB)
    const int tid = threadIdx.x;
    const int tx = tid & 15;       // 16 col-groups of 4 cols (64 cols)
    const int ty = tid >> 4;       // 16 row-groups of 8 rows (128 rows)
    const int r0 = blockIdx.x * 128;
    const int c0 = blockIdx.y * 64;

    // W halves: 128 rows x 16 float4 = 2048 float4 each; 8 per thread
#pragma unroll
    for (int i = 0; i < 8; i++) {
        int f = tid + 256 * i;
        int r = f >> 4, c4 = f & 15;
        ((float4*)W1s)[f] = ((const float4*)&W1[(size_t)r * DD + c0])[c4];
        ((float4*)W2s)[f] = ((const float4*)&W2[(size_t)r * DD + c0])[c4];
    }
    // X tile 128x128 = 4096 float4; 16 per thread; BN affine folded in
#pragma unroll
    for (int i = 0; i < 16; i++) {
        int f = tid + 256 * i;
        int row = r0 + (f >> 5);
        int j4 = f & 31;
        float4 v = make_float4(0.f, 0.f, 0.f, 0.f);
        if (row < nrows) {
            v = ((const float4*)(X + (size_t)row * DD))[j4];
            if (cs) {
                float4 s4 = ((const float4*)cs)[j4];
                float4 h4 = ((const float4*)cb)[j4];
                v.x = fmaf(v.x, s4.x, h4.x);
                v.y = fmaf(v.y, s4.y, h4.y);
                v.z = fmaf(v.z, s4.z, h4.z);
                v.w = fmaf(v.w, s4.w, h4.w);
            }
        }
        ((float4*)Xs)[f] = v;
    }
    __syncthreads();

    unsigned long long a1[8][2], a2[8][2];
#pragma unroll
    for (int m = 0; m < 8; m++) {
        a1[m][0] = a1[m][1] = 0ull;
        a2[m][0] = a2[m][1] = 0ull;
    }

#pragma unroll 4
    for (int k = 0; k < 128; k += 4) {
        float4 xv[8];
#pragma unroll
        for (int m = 0; m < 8; m++)
            xv[m] = *(const float4*)&Xs[(ty * 8 + m) * 128 + k];
#pragma unroll
        for (int kk = 0; kk < 4; kk++) {
            ulonglong2 w1 = *(const ulonglong2*)&W1s[(k + kk) * 64 + tx * 4];
            ulonglong2 w2 = *(const ulonglong2*)&W2s[(k + kk) * 64 + tx * 4];
#pragma unroll
            for (int m = 0; m < 8; m++) {
                float x = (kk == 0) ? xv[m].x : (kk == 1) ? xv[m].y
                        : (kk == 2) ? xv[m].z : xv[m].w;
                unsigned long long xp = pack_dup(x);
                ffma2(a1[m][0], xp, w1.x);
                ffma2(a1[m][1], xp, w1.y);
                ffma2(a2[m][0], xp, w2.x);
                ffma2(a2[m][1], xp, w2.y);
            }
        }
    }

    float4 b4 = ((const float4*)&b2[c0])[tx];
#pragma unroll
    for (int m = 0; m < 8; m++) {
        int row = r0 + ty * 8 + m;
        if (row < nrows) {
            float s = rs[row];
            float2 p0 = unpack2(a1[m][0]);
            float2 p1 = unpack2(a1[m][1]);
            float4 o1 = make_float4(p0.x * s, p0.y * s, p1.x * s, p1.y * s);
            ((float4*)(Y1 + (size_t)row * DD + c0))[tx] = o1;
            float2 q0 = unpack2(a2[m][0]);
            float2 q1 = unpack2(a2[m][1]);
            float4 o2;
            o2.x = fmaxf(q0.x + b4.x, 0.f);
            o2.y = fmaxf(q0.y + b4.y, 0.f);
            o2.z = fmaxf(q1.x + b4.z, 0.f);
            o2.w = fmaxf(q1.y + b4.w, 0.f);
            ((float4*)(Y2 + (size_t)row * DD + c0))[tx] = o2;
        }
    }
}

// ---------------- CSR aggregation + combine + BN stats (fused) ----------------
__global__ void k_agg(const float* __restrict__ bg, int zpool) {
    __shared__ float ssum[8][DD];
    __shared__ float ssq[8][DD];
    int tid = threadIdx.x;
    int w = tid >> 5;
    int lane = tid & 31;

    if (zpool) {
        int gstep = gridDim.x * blockDim.x;
        int gidx = blockIdx.x * blockDim.x + tid;
        for (int i = gidx; i < GG * DD; i += gstep) g_gsum[i] = 0.f;
        for (int i = gidx; i < (MM + 1) * DD; i += gstep) g_msum[i] = 0.f;
        for (int i = gidx; i < GG; i += gstep) g_gcnt[i] = 0.f;
        for (int i = gidx; i < MM + 1; i += gstep) g_mcnt[i] = 0.f;
    }

    int node = blockIdx.x * 8 + w;
    float4 y = make_float4(0.f, 0.f, 0.f, 0.f);
    if (node < NN) {
        int e0 = g_rowstart[node], e1 = g_rowstart[node + 1];
        float4 acc0 = make_float4(0.f, 0.f, 0.f, 0.f);
        float4 acc1 = make_float4(0.f, 0.f, 0.f, 0.f);
        float4 acc2 = make_float4(0.f, 0.f, 0.f, 0.f);
        float4 acc3 = make_float4(0.f, 0.f, 0.f, 0.f);
        int e = e0;
        for (; e + 4 <= e1; e += 4) {
            int s0 = g_csr_src[e], s1 = g_csr_src[e + 1];
            int s2 = g_csr_src[e + 2], s3 = g_csr_src[e + 3];
            float4 v0 = ((const float4*)(g_bufB + (size_t)s0 * DD))[lane];
            float4 v1 = ((const float4*)(g_bufB + (size_t)s1 * DD))[lane];
            float4 v2 = ((const float4*)(g_bufB + (size_t)s2 * DD))[lane];
            float4 v3 = ((const float4*)(g_bufB + (size_t)s3 * DD))[lane];
            acc0.x += v0.x; acc0.y += v0.y; acc0.z += v0.z; acc0.w += v0.w;
            acc1.x += v1.x; acc1.y += v1.y; acc1.z += v1.z; acc1.w += v1.w;
            acc2.x += v2.x; acc2.y += v2.y; acc2.z += v2.z; acc2.w += v2.w;
            acc3.x += v3.x; acc3.y += v3.y; acc3.z += v3.z; acc3.w += v3.w;
        }
        for (; e < e1; e++) {
            int s0 = g_csr_src[e];
            float4 v0 = ((const float4*)(g_bufB + (size_t)s0 * DD))[lane];
            acc0.x += v0.x; acc0.y += v0.y; acc0.z += v0.z; acc0.w += v0.w;
        }
        acc0.x += acc1.x + acc2.x + acc3.x;
        acc0.y += acc1.y + acc2.y + acc3.y;
        acc0.z += acc1.z + acc2.z + acc3.z;
        acc0.w += acc1.w + acc2.w + acc3.w;

        float nd = g_norm_dst[node];
        float4 b4 = ((const float4*)bg)[lane];
        float4 r = ((const float4*)(g_bufR + (size_t)node * DD))[lane];
        y.x = fmaxf(fmaf(acc0.x, nd, b4.x), 0.f) + r.x;
        y.y = fmaxf(fmaf(acc0.y, nd, b4.y), 0.f) + r.y;
        y.z = fmaxf(fmaf(acc0.z, nd, b4.z), 0.f) + r.z;
        y.w = fmaxf(fmaf(acc0.w, nd, b4.w), 0.f) + r.w;
        ((float4*)(g_bufA + (size_t)node * DD))[lane] = y;
    }
    ((float4*)&ssum[w][0])[lane] = y;
    float4 y2 = make_float4(y.x * y.x, y.y * y.y, y.z * y.z, y.w * y.w);
    ((float4*)&ssq[w][0])[lane] = y2;
    __syncthreads();
    if (tid < DD) {
        float s = 0.f;
#pragma unroll
        for (int i = 0; i < 8; i++) s += ssum[i][tid];
        atomicAdd(&g_stats[tid], s);
    } else {
        int j = tid - DD;
        float s = 0.f;
#pragma unroll
        for (int i = 0; i < 8; i++) s += ssq[i][j];
        atomicAdd(&g_stats[DD + j], s);
    }
}

// ---------------- BN prep ----------------
__global__ void k_bnprep(const float* __restrict__ gamma, const float* __restrict__ beta) {
    int j = threadIdx.x;
    float invN = 1.0f / (float)NN;
    float mu = g_stats[j] * invN;
    float var = fmaxf(g_stats[DD + j] * invN - mu * mu, 0.f);
    float s = gamma[j] * rsqrtf(var + BN_EPS);
    g_cs[j] = s;
    g_cb[j] = beta[j] - mu * s;
    g_stats[j] = 0.f;
    g_stats[DD + j] = 0.f;
}

// ---------------- pooling (BN affine applied here) + counts ----------------
__global__ void k_pool(const int* __restrict__ gid, const int* __restrict__ mid) {
    int g = blockIdx.x * blockDim.x + threadIdx.x;
    int node = g >> 5;
    int lane = threadIdx.x & 31;
    if (node >= NN) return;
    float4 v = ((const float4*)(g_bufA + (size_t)node * DD))[lane];
    float4 s4 = ((const float4*)g_cs)[lane];
    float4 h4 = ((const float4*)g_cb)[lane];
    v.x = fmaf(v.x, s4.x, h4.x);
    v.y = fmaf(v.y, s4.y, h4.y);
    v.z = fmaf(v.z, s4.z, h4.z);
    v.w = fmaf(v.w, s4.w, h4.w);
    int gi = gid[node], mi = mid[node];
    atomicAdd(((float4*)(g_gsum + (size_t)gi * DD)) + lane, v);
    atomicAdd(((float4*)(g_msum + (size_t)mi * DD)) + lane, v);
    if (lane == 0) {
        atomicAdd(&g_gcnt[gi], 1.0f);
        atomicAdd(&g_mcnt[mi], 1.0f);
    }
}

__global__ void k_finalize(float* __restrict__ out_gf) {
    int idx = blockIdx.x * blockDim.x + threadIdx.x;
    if (idx >= (GG + MM) * DD) return;
    int row = idx / DD, j = idx % DD;
    float v;
    if (row < GG) {
        v = g_gsum[row * DD + j] / fmaxf(g_gcnt[row], 1.0f);
        out_gf[row * DD + j] = v;
    } else {
        int mrow = row - GG + 1;  // drop motif segment 0
        v = g_msum[mrow * DD + j] / fmaxf(g_mcnt[mrow], 1.0f);
    }
    g_headin[idx] = v;
}

// ---------------- fp32 tiled GEMM with f32x2 (head MLP) ----------------
__global__ void k_gemm(const float* __restrict__ X, const float* __restrict__ W,
                       const float* __restrict__ bias,
                       float* __restrict__ Y, int nrows, int K, int ncols, int do_relu) {
    extern __shared__ float sm[];
    float* Ws = sm;               // 128*128
    float* Xs = sm + 128 * 128;   // 64*128
    const int tid = threadIdx.x;
    const int tx = tid & 31;
    const int ty = tid >> 5;
    const int r0 = blockIdx.x * 64;
    const int c0 = blockIdx.y * 128;

    unsigned long long acc[8][2];
#pragma unroll
    for (int m = 0; m < 8; m++) acc[m][0] = acc[m][1] = 0ull;

    for (int kb = 0; kb < K; kb += 128) {
#pragma unroll
        for (int i = 0; i < 16; i++) {
            int f = tid + 256 * i;
            int r = f >> 5, c4 = f & 31;
            ((float4*)Ws)[f] = *(const float4*)&W[(size_t)(kb + r) * ncols + c0 + c4 * 4];
        }
#pragma unroll
        for (int i = 0; i < 8; i++) {
            int f = tid + 256 * i;
            int m = f >> 5, k4 = f & 31;
            int row = r0 + m;
            float4 v = make_float4(0.f, 0.f, 0.f, 0.f);
            if (row < nrows) v = *(const float4*)&X[(size_t)row * K + kb + k4 * 4];
            ((float4*)Xs)[f] = v;
        }
        __syncthreads();

#pragma unroll 2
        for (int k = 0; k < 128; k += 4) {
            float4 xv[8];
#pragma unroll
            for (int m = 0; m < 8; m++)
                xv[m] = *(const float4*)&Xs[(ty * 8 + m) * 128 + k];
#pragma unroll
            for (int kk = 0; kk < 4; kk++) {
                ulonglong2 w = *(const ulonglong2*)&Ws[(k + kk) * 128 + tx * 4];
#pragma unroll
                for (int m = 0; m < 8; m++) {
                    float x = (kk == 0) ? xv[m].x : (kk == 1) ? xv[m].y
                            : (kk == 2) ? xv[m].z : xv[m].w;
                    unsigned long long xp = pack_dup(x);
                    ffma2(acc[m][0], xp, w.x);
                    ffma2(acc[m][1], xp, w.y);
                }
            }
        }
        __syncthreads();
    }

    float4 b4 = make_float4(0.f, 0.f, 0.f, 0.f);
    if (bias) b4 = *(const float4*)&bias[c0 + tx * 4];
#pragma unroll
    for (int m = 0; m < 8; m++) {
        int row = r0 + ty * 8 + m;
        if (row < nrows) {
            float2 p0 = unpack2(acc[m][0]);
            float2 p1 = unpack2(acc[m][1]);
            float4 o;
            o.x = p0.x + b4.x; o.y = p0.y + b4.y;
            o.z = p1.x + b4.z; o.w = p1.y + b4.w;
            if (do_relu) {
                o.x = fmaxf(o.x, 0.f); o.y = fmaxf(o.y, 0.f);
                o.z = fmaxf(o.z, 0.f); o.w = fmaxf(o.w, 0.f);
            }
            *(float4*)&Y[(size_t)row * ncols + c0 + tx * 4] = o;
        }
    }
}

// ---------------- launch ----------------
extern "C" void kernel_launch(void* const* d_in, const int* in_sizes, int n_in,
                              void* d_out, int out_size) {
    const float* node_feats = (const float*)d_in[0];
    const int*   src        = (const int*)d_in[1];
    const int*   dst        = (const int*)d_in[2];
    const int*   gid        = (const int*)d_in[3];
    const int*   mid        = (const int*)d_in[4];
    const float* Wg         = (const float*)d_in[5];
    const float* bg         = (const float*)d_in[6];
    const float* Wr         = (const float*)d_in[7];
    const float* br         = (const float*)d_in[8];
    const float* gamma      = (const float*)d_in[9];
    const float* beta       = (const float*)d_in[10];
    const float* W_feat     = (const float*)d_in[11];
    const float* b_feat     = (const float*)d_in[12];
    const float* W1         = (const float*)d_in[13];
    const float* b1         = (const float*)d_in[14];
    const float* W2         = (const float*)d_in[15];
    const float* b2         = (const float*)d_in[16];
    float* out = (float*)d_out;

    void *pA, *pns, *pcs, *pcb, *phin, *ph1, *ph2, *pB, *pR;
    cudaGetSymbolAddress(&pA, g_bufA);
    cudaGetSymbolAddress(&pB, g_bufB);
    cudaGetSymbolAddress(&pR, g_bufR);
    cudaGetSymbolAddress(&pns, g_norm_src);
    cudaGetSymbolAddress(&pcs, g_cs);
    cudaGetSymbolAddress(&pcb, g_cb);
    cudaGetSymbolAddress(&phin, g_headin);
    cudaGetSymbolAddress(&ph1, g_head1);
    cudaGetSymbolAddress(&ph2, g_head2);

    const int SMEM_G = (128 * 128 + 64 * 128) * 4;            // 96 KB (head gemm)
    const int SMEM_D = (128 * 128 + 2 * 128 * 64) * 4;        // 128 KB (dual gemm)
    cudaFuncSetAttribute(k_gemm, cudaFuncAttributeMaxDynamicSharedMemorySize, SMEM_G);
    cudaFuncSetAttribute(k_dualgemm, cudaFuncAttributeMaxDynamicSharedMemorySize, SMEM_D);

    const int gemm_rows = (NN + 127) / 128;   // 391
    const int agg_blocks = (NN + 7) / 8;      // 6250

    // ---- setup: degree histogram + norms (3 launches) ----
    k_zero<<<(NN + 255) / 256, 256>>>();
    k_hist<<<(EE + 255) / 256, 256>>>(src, dst);
    k_norms<<<(NN + 255) / 256, 256>>>();

    // ---- layer-0 dual GEMM as 4th launch (captured by ncu) ----
    k_dualgemm<<<dim3(gemm_rows, 2), 256, SMEM_D>>>(
        node_feats, Wg, Wr, br, (const float*)pns,
        nullptr, nullptr, (float*)pB, (float*)pR, NN);

    // ---- CSR build (stream-ordered before k_agg) ----
    k_scan1<<<SCAN_B, 256>>>();
    k_scan2<<<1, 256>>>();
    k_scan3<<<SCAN_B, 256>>>();
    k_place<<<(EE + 255) / 256, 256>>>(src, dst);

    for (int l = 0; l < LL; l++) {
        if (l > 0) {
            k_dualgemm<<<dim3(gemm_rows, 2), 256, SMEM_D>>>(
                (const float*)pA, Wg + (size_t)l * DD * DD, Wr + (size_t)l * DD * DD,
                br + (size_t)l * DD, (const float*)pns,
                (const float*)pcs, (const float*)pcb,
                (float*)pB, (float*)pR, NN);
        }

        // A = relu(agg*nd + bg) + R; BN stats accumulated; layer 2 zeroes pool bufs
        k_agg<<<agg_blocks, 256>>>(bg + (size_t)l * DD, (l == LL - 1) ? 1 : 0);

        // fold BN into affine cs/cb for next consumer; resets stats
        k_bnprep<<<1, DD>>>(gamma + (size_t)l * DD, beta + (size_t)l * DD);
    }

    // ---- pooling (applies layer-2 BN affine) ----
    k_pool<<<(NN * 32 + 255) / 256, 256>>>(gid, mid);
    k_finalize<<<((GG + MM) * DD + 255) / 256, 256>>>(out);

    // ---- head MLP on [graph_feats ; h_sub] = 2560 rows ----
    const int HR = GG + MM;
    const int hblocks = (HR + 63) / 64;  // 40
    k_gemm<<<dim3(hblocks, FFN / 128), 256, SMEM_G>>>(
        (const float*)phin, W_feat, b_feat, (float*)ph1, HR, DD, FFN, 0);
    k_gemm<<<dim3(hblocks, FFN / 128), 256, SMEM_G>>>(
        (const float*)ph1, W1, b1, (float*)ph2, HR, FFN, FFN, 1);
    k_gemm<<<dim3(hblocks, 1), 256, SMEM_G>>>(
        (const float*)ph2, W2, b2, out + (size_t)GG * DD, HR, FFN, DD, 0);
}

// round 8
// speedup vs baseline: 1.0256x; 1.0256x over previous
#include <cuda_runtime.h>
#include <cuda_bf16.h>
#include <cstddef>

#define NN 50000
#define EE 600000
#define GG 512
#define MM 2048
#define DD 128
#define FFN 256
#define LL 3
#define BN_EPS 1e-5f
#define SCAN_B 196   // ceil(NN/256)

// ---------------- scratch (device globals) ----------------
__device__ float g_bufA[NN * DD];   // layer output h
__device__ float g_bufB[NN * DD];   // hw branch
__device__ float g_bufR[NN * DD];   // residual branch
__device__ int   g_degin[NN];
__device__ int   g_degout[NN];
__device__ int   g_cursor[NN];
__device__ int   g_rowstart[NN + 1];
__device__ int   g_csr_src[EE];
__device__ int   g_bsum[SCAN_B];
__device__ int   g_boff[SCAN_B];
__device__ float g_norm_src[NN];
__device__ float g_norm_dst[NN];
__device__ float g_stats[2 * DD];
__device__ float g_cs[DD];
__device__ float g_cb[DD];
__device__ float g_gsum[GG * DD];
__device__ float g_gcnt[GG];
__device__ float g_msum[(MM + 1) * DD];
__device__ float g_mcnt[MM + 1];
__device__ float g_headin[(GG + MM) * DD];
__device__ float g_head1[(GG + MM) * FFN];
__device__ float g_head2[(GG + MM) * FFN];

// ---------------- f32x2 helpers ----------------
__device__ __forceinline__ unsigned long long pack_dup(float x) {
    unsigned long long p;
    unsigned int xb = __float_as_uint(x);
    asm("mov.b64 %0, {%1, %1};" : "=l"(p) : "r"(xb));
    return p;
}
__device__ __forceinline__ void ffma2(unsigned long long& acc, unsigned long long a,
                                      unsigned long long b) {
    asm("fma.rn.f32x2 %0, %1, %2, %0;" : "+l"(acc) : "l"(a), "l"(b));
}
__device__ __forceinline__ float2 unpack2(unsigned long long a) {
    float lo, hi;
    asm("mov.b64 {%0, %1}, %2;" : "=f"(lo), "=f"(hi) : "l"(a));
    return make_float2(lo, hi);
}

// ---------------- setup ----------------
__global__ void k_zero() {
    int i = blockIdx.x * blockDim.x + threadIdx.x;
    if (i < NN) { g_degin[i] = 0; g_degout[i] = 0; }
}

__global__ void k_hist(const int* __restrict__ src, const int* __restrict__ dst) {
    int e = blockIdx.x * blockDim.x + threadIdx.x;
    if (e < EE) {
        atomicAdd(&g_degout[src[e]], 1);
        atomicAdd(&g_degin[dst[e]], 1);
    }
}

__global__ void k_norms() {
    int i = blockIdx.x * blockDim.x + threadIdx.x;
    if (i < NN) {
        g_norm_src[i] = rsqrtf(fmaxf((float)g_degout[i], 1.0f));
        g_norm_dst[i] = rsqrtf(fmaxf((float)g_degin[i], 1.0f));
    }
    if (i < 2 * DD) g_stats[i] = 0.f;   // zero BN stats for layer 0
}

// ---------------- multi-block scan of g_degin -> g_rowstart ----------------
__global__ void k_scan1() {          // grid SCAN_B, block 256: block sums + zero cursor
    __shared__ int sh[256];
    int tid = threadIdx.x;
    int i = blockIdx.x * 256 + tid;
    int v = (i < NN) ? g_degin[i] : 0;
    if (i < NN) g_cursor[i] = 0;
    sh[tid] = v;
    __syncthreads();
    for (int off = 128; off > 0; off >>= 1) {
        if (tid < off) sh[tid] += sh[tid + off];
        __syncthreads();
    }
    if (tid == 0) g_bsum[blockIdx.x] = sh[0];
}

__global__ void k_scan2() {          // 1 block 256: exclusive scan of SCAN_B partials
    __shared__ int sh[256];
    int tid = threadIdx.x;
    int v = (tid < SCAN_B) ? g_bsum[tid] : 0;
    sh[tid] = v;
    __syncthreads();
    for (int off = 1; off < 256; off <<= 1) {
        int t = (tid >= off) ? sh[tid - off] : 0;
        __syncthreads();
        sh[tid] += t;
        __syncthreads();
    }
    if (tid < SCAN_B) g_boff[tid] = sh[tid] - v;
}

__global__ void k_scan3() {          // grid SCAN_B, block 256: local scan + offset
    __shared__ int sh[256];
    int tid = threadIdx.x;
    int i = blockIdx.x * 256 + tid;
    int v = (i < NN) ? g_degin[i] : 0;
    sh[tid] = v;
    __syncthreads();
    for (int off = 1; off < 256; off <<= 1) {
        int t = (tid >= off) ? sh[tid - off] : 0;
        __syncthreads();
        sh[tid] += t;
        __syncthreads();
    }
    if (i < NN) g_rowstart[i] = sh[tid] - v + g_boff[blockIdx.x];
    if (blockIdx.x == 0 && tid == 0) g_rowstart[NN] = EE;
}

__global__ void k_place(const int* __restrict__ src, const int* __restrict__ dst) {
    int e = blockIdx.x * blockDim.x + threadIdx.x;
    if (e < EE) {
        int d = dst[e];
        int slot = atomicAdd(&g_cursor[d], 1);
        g_csr_src[g_rowstart[d] + slot] = src[e];
    }
}

// ---------------- fused dual GEMM (fp32 FFMA2), 128x64 tile, K chunked by 64 ----------------
// Y1 = rs .* (Xn @ W1)      Xn = X*cs + cb (identity if cs==nullptr)
// Y2 = relu(Xn @ W2 + b2)
// 8 rows/thread, 4 cols, both matrices. smem 96 KB -> 2 CTAs/SM (16 warps).
// Per k-quad per thread: 16 LDS.128 vs 128 FFMA2 (8:1 -> LSU/FMA balanced).
__global__ void __launch_bounds__(256, 2)
k_dualgemm(const float* __restrict__ X,
           const float* __restrict__ W1,
           const float* __restrict__ W2,
           const float* __restrict__ b2,
           const float* __restrict__ rs,
           const float* __restrict__ cs,
           const float* __restrict__ cb,
           float* __restrict__ Y1, float* __restrict__ Y2,
           int nrows) {
    extern __shared__ float sm[];
    float* Xs  = sm;               // 128*64 (32 KB), reloaded per K-chunk
    float* W1s = sm + 128 * 64;    // 128*64 (32 KB), K-resident
    float* W2s = W1s + 128 * 64;   // 128*64 (32 KB), K-resident
    const int tid = threadIdx.x;
    const int tx = tid & 15;       // 16 col-groups of 4 cols (64 cols)
    const int ty = tid >> 4;       // 16 row-groups of 8 rows (128 rows)
    const int r0 = blockIdx.x * 128;
    const int c0 = blockIdx.y * 64;

    // W tiles: 128 K-rows x 16 float4 = 2048 float4 each; 8 per thread
#pragma unroll
    for (int i = 0; i < 8; i++) {
        int f = tid + 256 * i;
        int r = f >> 4, c4 = f & 15;
        ((float4*)W1s)[f] = ((const float4*)&W1[(size_t)r * DD + c0])[c4];
        ((float4*)W2s)[f] = ((const float4*)&W2[(size_t)r * DD + c0])[c4];
    }

    unsigned long long a1[8][2], a2[8][2];
#pragma unroll
    for (int m = 0; m < 8; m++) {
        a1[m][0] = a1[m][1] = 0ull;
        a2[m][0] = a2[m][1] = 0ull;
    }

    for (int kc = 0; kc < 2; kc++) {
        if (kc) __syncthreads();   // drain readers of previous Xs chunk
        // Xs chunk: 128 rows x 64 cols = 2048 float4; 8 per thread; BN affine folded in
#pragma unroll
        for (int i = 0; i < 8; i++) {
            int f = tid + 256 * i;
            int row = r0 + (f >> 4);
            int j4 = f & 15;
            float4 v = make_float4(0.f, 0.f, 0.f, 0.f);
            if (row < nrows) {
                v = ((const float4*)(X + (size_t)row * DD + kc * 64))[j4];
                if (cs) {
                    float4 s4 = ((const float4*)(cs + kc * 64))[j4];
                    float4 h4 = ((const float4*)(cb + kc * 64))[j4];
                    v.x = fmaf(v.x, s4.x, h4.x);
                    v.y = fmaf(v.y, s4.y, h4.y);
                    v.z = fmaf(v.z, s4.z, h4.z);
                    v.w = fmaf(v.w, s4.w, h4.w);
                }
            }
            ((float4*)Xs)[f] = v;
        }
        __syncthreads();

#pragma unroll 4
        for (int k = 0; k < 64; k += 4) {
            float4 xv[8];
#pragma unroll
            for (int m = 0; m < 8; m++)
                xv[m] = *(const float4*)&Xs[(ty * 8 + m) * 64 + k];
#pragma unroll
            for (int kk = 0; kk < 4; kk++) {
                int kg = kc * 64 + k + kk;
                ulonglong2 w1 = *(const ulonglong2*)&W1s[kg * 64 + tx * 4];
                ulonglong2 w2 = *(const ulonglong2*)&W2s[kg * 64 + tx * 4];
#pragma unroll
                for (int m = 0; m < 8; m++) {
                    float x = (kk == 0) ? xv[m].x : (kk == 1) ? xv[m].y
                            : (kk == 2) ? xv[m].z : xv[m].w;
                    unsigned long long xp = pack_dup(x);
                    ffma2(a1[m][0], xp, w1.x);
                    ffma2(a1[m][1], xp, w1.y);
                    ffma2(a2[m][0], xp, w2.x);
                    ffma2(a2[m][1], xp, w2.y);
                }
            }
        }
    }

    float4 b4 = ((const float4*)&b2[c0])[tx];
#pragma unroll
    for (int m = 0; m < 8; m++) {
        int row = r0 + ty * 8 + m;
        if (row < nrows) {
            float s = rs[row];
            float2 p0 = unpack2(a1[m][0]);
            float2 p1 = unpack2(a1[m][1]);
            float4 o1 = make_float4(p0.x * s, p0.y * s, p1.x * s, p1.y * s);
            ((float4*)(Y1 + (size_t)row * DD + c0))[tx] = o1;
            float2 q0 = unpack2(a2[m][0]);
            float2 q1 = unpack2(a2[m][1]);
            float4 o2;
            o2.x = fmaxf(q0.x + b4.x, 0.f);
            o2.y = fmaxf(q0.y + b4.y, 0.f);
            o2.z = fmaxf(q1.x + b4.z, 0.f);
            o2.w = fmaxf(q1.y + b4.w, 0.f);
            ((float4*)(Y2 + (size_t)row * DD + c0))[tx] = o2;
        }
    }
}

// ---------------- CSR aggregation + combine + BN stats (fused) ----------------
__global__ void k_agg(const float* __restrict__ bg, int zpool) {
    __shared__ float ssum[8][DD];
    __shared__ float ssq[8][DD];
    int tid = threadIdx.x;
    int w = tid >> 5;
    int lane = tid & 31;

    if (zpool) {
        int gstep = gridDim.x * blockDim.x;
        int gidx = blockIdx.x * blockDim.x + tid;
        for (int i = gidx; i < GG * DD; i += gstep) g_gsum[i] = 0.f;
        for (int i = gidx; i < (MM + 1) * DD; i += gstep) g_msum[i] = 0.f;
        for (int i = gidx; i < GG; i += gstep) g_gcnt[i] = 0.f;
        for (int i = gidx; i < MM + 1; i += gstep) g_mcnt[i] = 0.f;
    }

    int node = blockIdx.x * 8 + w;
    float4 y = make_float4(0.f, 0.f, 0.f, 0.f);
    if (node < NN) {
        int e0 = g_rowstart[node], e1 = g_rowstart[node + 1];
        float4 acc0 = make_float4(0.f, 0.f, 0.f, 0.f);
        float4 acc1 = make_float4(0.f, 0.f, 0.f, 0.f);
        float4 acc2 = make_float4(0.f, 0.f, 0.f, 0.f);
        float4 acc3 = make_float4(0.f, 0.f, 0.f, 0.f);
        int e = e0;
        for (; e + 4 <= e1; e += 4) {
            int s0 = g_csr_src[e], s1 = g_csr_src[e + 1];
            int s2 = g_csr_src[e + 2], s3 = g_csr_src[e + 3];
            float4 v0 = ((const float4*)(g_bufB + (size_t)s0 * DD))[lane];
            float4 v1 = ((const float4*)(g_bufB + (size_t)s1 * DD))[lane];
            float4 v2 = ((const float4*)(g_bufB + (size_t)s2 * DD))[lane];
            float4 v3 = ((const float4*)(g_bufB + (size_t)s3 * DD))[lane];
            acc0.x += v0.x; acc0.y += v0.y; acc0.z += v0.z; acc0.w += v0.w;
            acc1.x += v1.x; acc1.y += v1.y; acc1.z += v1.z; acc1.w += v1.w;
            acc2.x += v2.x; acc2.y += v2.y; acc2.z += v2.z; acc2.w += v2.w;
            acc3.x += v3.x; acc3.y += v3.y; acc3.z += v3.z; acc3.w += v3.w;
        }
        for (; e < e1; e++) {
            int s0 = g_csr_src[e];
            float4 v0 = ((const float4*)(g_bufB + (size_t)s0 * DD))[lane];
            acc0.x += v0.x; acc0.y += v0.y; acc0.z += v0.z; acc0.w += v0.w;
        }
        acc0.x += acc1.x + acc2.x + acc3.x;
        acc0.y += acc1.y + acc2.y + acc3.y;
        acc0.z += acc1.z + acc2.z + acc3.z;
        acc0.w += acc1.w + acc2.w + acc3.w;

        float nd = g_norm_dst[node];
        float4 b4 = ((const float4*)bg)[lane];
        float4 r = ((const float4*)(g_bufR + (size_t)node * DD))[lane];
        y.x = fmaxf(fmaf(acc0.x, nd, b4.x), 0.f) + r.x;
        y.y = fmaxf(fmaf(acc0.y, nd, b4.y), 0.f) + r.y;
        y.z = fmaxf(fmaf(acc0.z, nd, b4.z), 0.f) + r.z;
        y.w = fmaxf(fmaf(acc0.w, nd, b4.w), 0.f) + r.w;
        ((float4*)(g_bufA + (size_t)node * DD))[lane] = y;
    }
    ((float4*)&ssum[w][0])[lane] = y;
    float4 y2 = make_float4(y.x * y.x, y.y * y.y, y.z * y.z, y.w * y.w);
    ((float4*)&ssq[w][0])[lane] = y2;
    __syncthreads();
    if (tid < DD) {
        float s = 0.f;
#pragma unroll
        for (int i = 0; i < 8; i++) s += ssum[i][tid];
        atomicAdd(&g_stats[tid], s);
    } else {
        int j = tid - DD;
        float s = 0.f;
#pragma unroll
        for (int i = 0; i < 8; i++) s += ssq[i][j];
        atomicAdd(&g_stats[DD + j], s);
    }
}

// ---------------- BN prep ----------------
__global__ void k_bnprep(const float* __restrict__ gamma, const float* __restrict__ beta) {
    int j = threadIdx.x;
    float invN = 1.0f / (float)NN;
    float mu = g_stats[j] * invN;
    float var = fmaxf(g_stats[DD + j] * invN - mu * mu, 0.f);
    float s = gamma[j] * rsqrtf(var + BN_EPS);
    g_cs[j] = s;
    g_cb[j] = beta[j] - mu * s;
    g_stats[j] = 0.f;
    g_stats[DD + j] = 0.f;
}

// ---------------- pooling (BN affine applied here) + counts ----------------
__global__ void k_pool(const int* __restrict__ gid, const int* __restrict__ mid) {
    int g = blockIdx.x * blockDim.x + threadIdx.x;
    int node = g >> 5;
    int lane = threadIdx.x & 31;
    if (node >= NN) return;
    float4 v = ((const float4*)(g_bufA + (size_t)node * DD))[lane];
    float4 s4 = ((const float4*)g_cs)[lane];
    float4 h4 = ((const float4*)g_cb)[lane];
    v.x = fmaf(v.x, s4.x, h4.x);
    v.y = fmaf(v.y, s4.y, h4.y);
    v.z = fmaf(v.z, s4.z, h4.z);
    v.w = fmaf(v.w, s4.w, h4.w);
    int gi = gid[node], mi = mid[node];
    atomicAdd(((float4*)(g_gsum + (size_t)gi * DD)) + lane, v);
    atomicAdd(((float4*)(g_msum + (size_t)mi * DD)) + lane, v);
    if (lane == 0) {
        atomicAdd(&g_gcnt[gi], 1.0f);
        atomicAdd(&g_mcnt[mi], 1.0f);
    }
}

__global__ void k_finalize(float* __restrict__ out_gf) {
    int idx = blockIdx.x * blockDim.x + threadIdx.x;
    if (idx >= (GG + MM) * DD) return;
    int row = idx / DD, j = idx % DD;
    float v;
    if (row < GG) {
        v = g_gsum[row * DD + j] / fmaxf(g_gcnt[row], 1.0f);
        out_gf[row * DD + j] = v;
    } else {
        int mrow = row - GG + 1;  // drop motif segment 0
        v = g_msum[mrow * DD + j] / fmaxf(g_mcnt[mrow], 1.0f);
    }
    g_headin[idx] = v;
}

// ---------------- fp32 tiled GEMM with f32x2 (head MLP) ----------------
__global__ void k_gemm(const float* __restrict__ X, const float* __restrict__ W,
                       const float* __restrict__ bias,
                       float* __restrict__ Y, int nrows, int K, int ncols, int do_relu) {
    extern __shared__ float sm[];
    float* Ws = sm;               // 128*128
    float* Xs = sm + 128 * 128;   // 64*128
    const int tid = threadIdx.x;
    const int tx = tid & 31;
    const int ty = tid >> 5;
    const int r0 = blockIdx.x * 64;
    const int c0 = blockIdx.y * 128;

    unsigned long long acc[8][2];
#pragma unroll
    for (int m = 0; m < 8; m++) acc[m][0] = acc[m][1] = 0ull;

    for (int kb = 0; kb < K; kb += 128) {
#pragma unroll
        for (int i = 0; i < 16; i++) {
            int f = tid + 256 * i;
            int r = f >> 5, c4 = f & 31;
            ((float4*)Ws)[f] = *(const float4*)&W[(size_t)(kb + r) * ncols + c0 + c4 * 4];
        }
#pragma unroll
        for (int i = 0; i < 8; i++) {
            int f = tid + 256 * i;
            int m = f >> 5, k4 = f & 31;
            int row = r0 + m;
            float4 v = make_float4(0.f, 0.f, 0.f, 0.f);
            if (row < nrows) v = *(const float4*)&X[(size_t)row * K + kb + k4 * 4];
            ((float4*)Xs)[f] = v;
        }
        __syncthreads();

#pragma unroll 2
        for (int k = 0; k < 128; k += 4) {
            float4 xv[8];
#pragma unroll
            for (int m = 0; m < 8; m++)
                xv[m] = *(const float4*)&Xs[(ty * 8 + m) * 128 + k];
#pragma unroll
            for (int kk = 0; kk < 4; kk++) {
                ulonglong2 w = *(const ulonglong2*)&Ws[(k + kk) * 128 + tx * 4];
#pragma unroll
                for (int m = 0; m < 8; m++) {
                    float x = (kk == 0) ? xv[m].x : (kk == 1) ? xv[m].y
                            : (kk == 2) ? xv[m].z : xv[m].w;
                    unsigned long long xp = pack_dup(x);
                    ffma2(acc[m][0], xp, w.x);
                    ffma2(acc[m][1], xp, w.y);
                }
            }
        }
        __syncthreads();
    }

    float4 b4 = make_float4(0.f, 0.f, 0.f, 0.f);
    if (bias) b4 = *(const float4*)&bias[c0 + tx * 4];
#pragma unroll
    for (int m = 0; m < 8; m++) {
        int row = r0 + ty * 8 + m;
        if (row < nrows) {
            float2 p0 = unpack2(acc[m][0]);
            float2 p1 = unpack2(acc[m][1]);
            float4 o;
            o.x = p0.x + b4.x; o.y = p0.y + b4.y;
            o.z = p1.x + b4.z; o.w = p1.y + b4.w;
            if (do_relu) {
                o.x = fmaxf(o.x, 0.f); o.y = fmaxf(o.y, 0.f);
                o.z = fmaxf(o.z, 0.f); o.w = fmaxf(o.w, 0.f);
            }
            *(float4*)&Y[(size_t)row * ncols + c0 + tx * 4] = o;
        }
    }
}

// ---------------- launch ----------------
extern "C" void kernel_launch(void* const* d_in, const int* in_sizes, int n_in,
                              void* d_out, int out_size) {
    const float* node_feats = (const float*)d_in[0];
    const int*   src        = (const int*)d_in[1];
    const int*   dst        = (const int*)d_in[2];
    const int*   gid        = (const int*)d_in[3];
    const int*   mid        = (const int*)d_in[4];
    const float* Wg         = (const float*)d_in[5];
    const float* bg         = (const float*)d_in[6];
    const float* Wr         = (const float*)d_in[7];
    const float* br         = (const float*)d_in[8];
    const float* gamma      = (const float*)d_in[9];
    const float* beta       = (const float*)d_in[10];
    const float* W_feat     = (const float*)d_in[11];
    const float* b_feat     = (const float*)d_in[12];
    const float* W1         = (const float*)d_in[13];
    const float* b1         = (const float*)d_in[14];
    const float* W2         = (const float*)d_in[15];
    const float* b2         = (const float*)d_in[16];
    float* out = (float*)d_out;

    void *pA, *pns, *pcs, *pcb, *phin, *ph1, *ph2, *pB, *pR;
    cudaGetSymbolAddress(&pA, g_bufA);
    cudaGetSymbolAddress(&pB, g_bufB);
    cudaGetSymbolAddress(&pR, g_bufR);
    cudaGetSymbolAddress(&pns, g_norm_src);
    cudaGetSymbolAddress(&pcs, g_cs);
    cudaGetSymbolAddress(&pcb, g_cb);
    cudaGetSymbolAddress(&phin, g_headin);
    cudaGetSymbolAddress(&ph1, g_head1);
    cudaGetSymbolAddress(&ph2, g_head2);

    const int SMEM_G = (128 * 128 + 64 * 128) * 4;            // 96 KB (head gemm)
    const int SMEM_D = (3 * 128 * 64) * 4;                    // 96 KB (dual gemm, 2 CTAs/SM)
    cudaFuncSetAttribute(k_gemm, cudaFuncAttributeMaxDynamicSharedMemorySize, SMEM_G);
    cudaFuncSetAttribute(k_dualgemm, cudaFuncAttributeMaxDynamicSharedMemorySize, SMEM_D);

    const int gemm_rows = (NN + 127) / 128;   // 391
    const int agg_blocks = (NN + 7) / 8;      // 6250

    // ---- setup: degree histogram + norms (3 launches) ----
    k_zero<<<(NN + 255) / 256, 256>>>();
    k_hist<<<(EE + 255) / 256, 256>>>(src, dst);
    k_norms<<<(NN + 255) / 256, 256>>>();

    // ---- layer-0 dual GEMM as 4th launch (captured by ncu) ----
    k_dualgemm<<<dim3(gemm_rows, 2), 256, SMEM_D>>>(
        node_feats, Wg, Wr, br, (const float*)pns,
        nullptr, nullptr, (float*)pB, (float*)pR, NN);

    // ---- CSR build (stream-ordered before k_agg) ----
    k_scan1<<<SCAN_B, 256>>>();
    k_scan2<<<1, 256>>>();
    k_scan3<<<SCAN_B, 256>>>();
    k_place<<<(EE + 255) / 256, 256>>>(src, dst);

    for (int l = 0; l < LL; l++) {
        if (l > 0) {
            k_dualgemm<<<dim3(gemm_rows, 2), 256, SMEM_D>>>(
                (const float*)pA, Wg + (size_t)l * DD * DD, Wr + (size_t)l * DD * DD,
                br + (size_t)l * DD, (const float*)pns,
                (const float*)pcs, (const float*)pcb,
                (float*)pB, (float*)pR, NN);
        }

        // A = relu(agg*nd + bg) + R; BN stats accumulated; layer 2 zeroes pool bufs
        k_agg<<<agg_blocks, 256>>>(bg + (size_t)l * DD, (l == LL - 1) ? 1 : 0);

        // fold BN into affine cs/cb for next consumer; resets stats
        k_bnprep<<<1, DD>>>(gamma + (size_t)l * DD, beta + (size_t)l * DD);
    }

    // ---- pooling (applies layer-2 BN affine) ----
    k_pool<<<(NN * 32 + 255) / 256, 256>>>(gid, mid);
    k_finalize<<<((GG + MM) * DD + 255) / 256, 256>>>(out);

    // ---- head MLP on [graph_feats ; h_sub] = 2560 rows ----
    const int HR = GG + MM;
    const int hblocks = (HR + 63) / 64;  // 40
    k_gemm<<<dim3(hblocks, FFN / 128), 256, SMEM_G>>>(
        (const float*)phin, W_feat, b_feat, (float*)ph1, HR, DD, FFN, 0);
    k_gemm<<<dim3(hblocks, FFN / 128), 256, SMEM_G>>>(
        (const float*)ph1, W1, b1, (float*)ph2, HR, FFN, FFN, 1);
    k_gemm<<<dim3(hblocks, 1), 256, SMEM_G>>>(
        (const float*)ph2, W2, b2, out + (size_t)GG * DD, HR, FFN, DD, 0);
}

// round 9
// speedup vs baseline: 1.0411x; 1.0152x over previous
#include <cuda_runtime.h>
#include <cuda_bf16.h>
#include <cstddef>

#define NN 50000
#define EE 600000
#define GG 512
#define MM 2048
#define DD 128
#define FFN 256
#define LL 3
#define BN_EPS 1e-5f
#define SCAN_B 196   // ceil(NN/256)

// ---------------- scratch (device globals) ----------------
__device__ float g_bufA[NN * DD];   // layer output h
__device__ float g_bufB[NN * DD];   // hw branch
__device__ float g_bufR[NN * DD];   // residual branch
__device__ int   g_degin[NN];
__device__ int   g_degout[NN];
__device__ int   g_cursor[NN];
__device__ int   g_rowstart[NN + 1];
__device__ int   g_csr_src[EE];
__device__ int   g_bsum[SCAN_B];
__device__ int   g_boff[SCAN_B];
__device__ float g_norm_src[NN];
__device__ float g_norm_dst[NN];
__device__ float g_stats[2 * DD];
__device__ float g_cs[DD];
__device__ float g_cb[DD];
__device__ float g_gsum[GG * DD];
__device__ float g_gcnt[GG];
__device__ float g_msum[(MM + 1) * DD];
__device__ float g_mcnt[MM + 1];
__device__ float g_headin[(GG + MM) * DD];
__device__ float g_head1[(GG + MM) * FFN];
__device__ float g_head2[(GG + MM) * FFN];

// ---------------- f32x2 helpers ----------------
__device__ __forceinline__ unsigned long long pack_dup(float x) {
    unsigned long long p;
    unsigned int xb = __float_as_uint(x);
    asm("mov.b64 %0, {%1, %1};" : "=l"(p) : "r"(xb));
    return p;
}
__device__ __forceinline__ void ffma2(unsigned long long& acc, unsigned long long a,
                                      unsigned long long b) {
    asm("fma.rn.f32x2 %0, %1, %2, %0;" : "+l"(acc) : "l"(a), "l"(b));
}
__device__ __forceinline__ float2 unpack2(unsigned long long a) {
    float lo, hi;
    asm("mov.b64 {%0, %1}, %2;" : "=f"(lo), "=f"(hi) : "l"(a));
    return make_float2(lo, hi);
}

// ---------------- setup ----------------
__global__ void k_zero() {
    int i = blockIdx.x * blockDim.x + threadIdx.x;
    if (i < NN) { g_degin[i] = 0; g_degout[i] = 0; }
}

__global__ void k_hist(const int* __restrict__ src, const int* __restrict__ dst) {
    int e = blockIdx.x * blockDim.x + threadIdx.x;
    if (e < EE) {
        atomicAdd(&g_degout[src[e]], 1);
        atomicAdd(&g_degin[dst[e]], 1);
    }
}

__global__ void k_norms() {
    int i = blockIdx.x * blockDim.x + threadIdx.x;
    if (i < NN) {
        g_norm_src[i] = rsqrtf(fmaxf((float)g_degout[i], 1.0f));
        g_norm_dst[i] = rsqrtf(fmaxf((float)g_degin[i], 1.0f));
    }
    if (i < 2 * DD) g_stats[i] = 0.f;   // zero BN stats for layer 0
}

// ---------------- multi-block scan of g_degin -> g_rowstart ----------------
__global__ void k_scan1() {
    __shared__ int sh[256];
    int tid = threadIdx.x;
    int i = blockIdx.x * 256 + tid;
    int v = (i < NN) ? g_degin[i] : 0;
    if (i < NN) g_cursor[i] = 0;
    sh[tid] = v;
    __syncthreads();
    for (int off = 128; off > 0; off >>= 1) {
        if (tid < off) sh[tid] += sh[tid + off];
        __syncthreads();
    }
    if (tid == 0) g_bsum[blockIdx.x] = sh[0];
}

__global__ void k_scan2() {
    __shared__ int sh[256];
    int tid = threadIdx.x;
    int v = (tid < SCAN_B) ? g_bsum[tid] : 0;
    sh[tid] = v;
    __syncthreads();
    for (int off = 1; off < 256; off <<= 1) {
        int t = (tid >= off) ? sh[tid - off] : 0;
        __syncthreads();
        sh[tid] += t;
        __syncthreads();
    }
    if (tid < SCAN_B) g_boff[tid] = sh[tid] - v;
}

__global__ void k_scan3() {
    __shared__ int sh[256];
    int tid = threadIdx.x;
    int i = blockIdx.x * 256 + tid;
    int v = (i < NN) ? g_degin[i] : 0;
    sh[tid] = v;
    __syncthreads();
    for (int off = 1; off < 256; off <<= 1) {
        int t = (tid >= off) ? sh[tid - off] : 0;
        __syncthreads();
        sh[tid] += t;
        __syncthreads();
    }
    if (i < NN) g_rowstart[i] = sh[tid] - v + g_boff[blockIdx.x];
    if (blockIdx.x == 0 && tid == 0) g_rowstart[NN] = EE;
}

__global__ void k_place(const int* __restrict__ src, const int* __restrict__ dst) {
    int e = blockIdx.x * blockDim.x + threadIdx.x;
    if (e < EE) {
        int d = dst[e];
        int slot = atomicAdd(&g_cursor[d], 1);
        g_csr_src[g_rowstart[d] + slot] = src[e];
    }
}

// ---------------- persistent fused dual GEMM (fp32 FFMA2) ----------------
// Y1 = rs .* (Xn @ W1)   Xn = X*cs + cb (identity if cs==nullptr)
// Y2 = relu(Xn @ W2 + b2)
// grid (148, 2): each CTA keeps its 64-col W1/W2 halves smem-resident and
// loops over 128-row tiles. 96 KB smem -> 2 CTAs/SM.
__global__ void __launch_bounds__(256, 2)
k_dualgemm(const float* __restrict__ X,
           const float* __restrict__ W1,
           const float* __restrict__ W2,
           const float* __restrict__ b2,
           const float* __restrict__ rs,
           const float* __restrict__ cs,
           const float* __restrict__ cb,
           float* __restrict__ Y1, float* __restrict__ Y2,
           int nrows) {
    extern __shared__ float sm[];
    float* Xs  = sm;               // 128*64 (32 KB), reloaded per K-chunk
    float* W1s = sm + 128 * 64;    // 128*64 (32 KB), resident
    float* W2s = W1s + 128 * 64;   // 128*64 (32 KB), resident
    const int tid = threadIdx.x;
    const int tx = tid & 15;       // 16 col-groups of 4 cols (64 cols)
    const int ty = tid >> 4;       // 16 row-groups of 8 rows (128 rows)
    const int c0 = blockIdx.y * 64;

    // W tiles: 128 K-rows x 16 float4 each; 8 per thread; loaded ONCE
#pragma unroll
    for (int i = 0; i < 8; i++) {
        int f = tid + 256 * i;
        int r = f >> 4, c4 = f & 15;
        ((float4*)W1s)[f] = ((const float4*)&W1[(size_t)r * DD + c0])[c4];
        ((float4*)W2s)[f] = ((const float4*)&W2[(size_t)r * DD + c0])[c4];
    }
    float4 b4 = ((const float4*)&b2[c0])[tx];

    for (int rt = blockIdx.x; rt * 128 < nrows; rt += gridDim.x) {
        const int r0 = rt * 128;

        unsigned long long a1[8][2], a2[8][2];
#pragma unroll
        for (int m = 0; m < 8; m++) {
            a1[m][0] = a1[m][1] = 0ull;
            a2[m][0] = a2[m][1] = 0ull;
        }

        for (int kc = 0; kc < 2; kc++) {
            __syncthreads();   // prior readers of Xs done (also orders W stores on 1st iter)
#pragma unroll
            for (int i = 0; i < 8; i++) {
                int f = tid + 256 * i;
                int row = r0 + (f >> 4);
                int j4 = f & 15;
                float4 v = make_float4(0.f, 0.f, 0.f, 0.f);
                if (row < nrows) {
                    v = ((const float4*)(X + (size_t)row * DD + kc * 64))[j4];
                    if (cs) {
                        float4 s4 = ((const float4*)(cs + kc * 64))[j4];
                        float4 h4 = ((const float4*)(cb + kc * 64))[j4];
                        v.x = fmaf(v.x, s4.x, h4.x);
                        v.y = fmaf(v.y, s4.y, h4.y);
                        v.z = fmaf(v.z, s4.z, h4.z);
                        v.w = fmaf(v.w, s4.w, h4.w);
                    }
                }
                ((float4*)Xs)[f] = v;
            }
            __syncthreads();

#pragma unroll 4
            for (int k = 0; k < 64; k += 4) {
                float4 xv[8];
#pragma unroll
                for (int m = 0; m < 8; m++)
                    xv[m] = *(const float4*)&Xs[(ty * 8 + m) * 64 + k];
#pragma unroll
                for (int kk = 0; kk < 4; kk++) {
                    int kg = kc * 64 + k + kk;
                    ulonglong2 w1 = *(const ulonglong2*)&W1s[kg * 64 + tx * 4];
                    ulonglong2 w2 = *(const ulonglong2*)&W2s[kg * 64 + tx * 4];
#pragma unroll
                    for (int m = 0; m < 8; m++) {
                        float x = (kk == 0) ? xv[m].x : (kk == 1) ? xv[m].y
                                : (kk == 2) ? xv[m].z : xv[m].w;
                        unsigned long long xp = pack_dup(x);
                        ffma2(a1[m][0], xp, w1.x);
                        ffma2(a1[m][1], xp, w1.y);
                        ffma2(a2[m][0], xp, w2.x);
                        ffma2(a2[m][1], xp, w2.y);
                    }
                }
            }
        }

#pragma unroll
        for (int m = 0; m < 8; m++) {
            int row = r0 + ty * 8 + m;
            if (row < nrows) {
                float s = rs[row];
                float2 p0 = unpack2(a1[m][0]);
                float2 p1 = unpack2(a1[m][1]);
                float4 o1 = make_float4(p0.x * s, p0.y * s, p1.x * s, p1.y * s);
                ((float4*)(Y1 + (size_t)row * DD + c0))[tx] = o1;
                float2 q0 = unpack2(a2[m][0]);
                float2 q1 = unpack2(a2[m][1]);
                float4 o2;
                o2.x = fmaxf(q0.x + b4.x, 0.f);
                o2.y = fmaxf(q0.y + b4.y, 0.f);
                o2.z = fmaxf(q1.x + b4.z, 0.f);
                o2.w = fmaxf(q1.y + b4.w, 0.f);
                ((float4*)(Y2 + (size_t)row * DD + c0))[tx] = o2;
            }
        }
    }
}

// ---------------- CSR aggregation + combine + BN stats (+ pooling on last layer) ----------------
// y = relu(agg*nd + bg) + R.  zpool: zero pool buffers (layer 0).
// do_pool: accumulate RAW y into pool sums (BN affine applied later in finalize)
//          and skip the bufA store (nothing consumes layer-2 bufA).
__global__ void k_agg(const float* __restrict__ bg, int zpool, int do_pool,
                      const int* __restrict__ gid, const int* __restrict__ mid) {
    __shared__ float ssum[8][DD];
    __shared__ float ssq[8][DD];
    int tid = threadIdx.x;
    int w = tid >> 5;
    int lane = tid & 31;

    if (zpool) {
        int gstep = gridDim.x * blockDim.x;
        int gidx = blockIdx.x * blockDim.x + tid;
        for (int i = gidx; i < GG * DD; i += gstep) g_gsum[i] = 0.f;
        for (int i = gidx; i < (MM + 1) * DD; i += gstep) g_msum[i] = 0.f;
        for (int i = gidx; i < GG; i += gstep) g_gcnt[i] = 0.f;
        for (int i = gidx; i < MM + 1; i += gstep) g_mcnt[i] = 0.f;
    }

    int node = blockIdx.x * 8 + w;
    float4 y = make_float4(0.f, 0.f, 0.f, 0.f);
    if (node < NN) {
        int e0 = g_rowstart[node], e1 = g_rowstart[node + 1];
        float4 acc[8];
#pragma unroll
        for (int i = 0; i < 8; i++) acc[i] = make_float4(0.f, 0.f, 0.f, 0.f);
        int e = e0;
        for (; e + 8 <= e1; e += 8) {
            float4 v[8];
#pragma unroll
            for (int i = 0; i < 8; i++) {
                int s = g_csr_src[e + i];
                v[i] = ((const float4*)(g_bufB + (size_t)s * DD))[lane];
            }
#pragma unroll
            for (int i = 0; i < 8; i++) {
                acc[i].x += v[i].x; acc[i].y += v[i].y;
                acc[i].z += v[i].z; acc[i].w += v[i].w;
            }
        }
        if (e + 4 <= e1) {
            float4 v[4];
#pragma unroll
            for (int i = 0; i < 4; i++) {
                int s = g_csr_src[e + i];
                v[i] = ((const float4*)(g_bufB + (size_t)s * DD))[lane];
            }
#pragma unroll
            for (int i = 0; i < 4; i++) {
                acc[i].x += v[i].x; acc[i].y += v[i].y;
                acc[i].z += v[i].z; acc[i].w += v[i].w;
            }
            e += 4;
        }
        for (; e < e1; e++) {
            int s = g_csr_src[e];
            float4 v0 = ((const float4*)(g_bufB + (size_t)s * DD))[lane];
            acc[0].x += v0.x; acc[0].y += v0.y; acc[0].z += v0.z; acc[0].w += v0.w;
        }
#pragma unroll
        for (int i = 4; i < 8; i++) {
            acc[i - 4].x += acc[i].x; acc[i - 4].y += acc[i].y;
            acc[i - 4].z += acc[i].z; acc[i - 4].w += acc[i].w;
        }
        acc[0].x += acc[2].x + acc[1].x + acc[3].x;
        acc[0].y += acc[2].y + acc[1].y + acc[3].y;
        acc[0].z += acc[2].z + acc[1].z + acc[3].z;
        acc[0].w += acc[2].w + acc[1].w + acc[3].w;

        float nd = g_norm_dst[node];
        float4 b4 = ((const float4*)bg)[lane];
        float4 r = ((const float4*)(g_bufR + (size_t)node * DD))[lane];
        y.x = fmaxf(fmaf(acc[0].x, nd, b4.x), 0.f) + r.x;
        y.y = fmaxf(fmaf(acc[0].y, nd, b4.y), 0.f) + r.y;
        y.z = fmaxf(fmaf(acc[0].z, nd, b4.z), 0.f) + r.z;
        y.w = fmaxf(fmaf(acc[0].w, nd, b4.w), 0.f) + r.w;

        if (do_pool) {
            int gi = gid[node], mi = mid[node];
            atomicAdd(((float4*)(g_gsum + (size_t)gi * DD)) + lane, y);
            atomicAdd(((float4*)(g_msum + (size_t)mi * DD)) + lane, y);
            if (lane == 0) {
                atomicAdd(&g_gcnt[gi], 1.0f);
                atomicAdd(&g_mcnt[mi], 1.0f);
            }
        } else {
            ((float4*)(g_bufA + (size_t)node * DD))[lane] = y;
        }
    }
    ((float4*)&ssum[w][0])[lane] = y;
    float4 y2 = make_float4(y.x * y.x, y.y * y.y, y.z * y.z, y.w * y.w);
    ((float4*)&ssq[w][0])[lane] = y2;
    __syncthreads();
    if (tid < DD) {
        float s = 0.f;
#pragma unroll
        for (int i = 0; i < 8; i++) s += ssum[i][tid];
        atomicAdd(&g_stats[tid], s);
    } else {
        int j = tid - DD;
        float s = 0.f;
#pragma unroll
        for (int i = 0; i < 8; i++) s += ssq[i][j];
        atomicAdd(&g_stats[DD + j], s);
    }
}

// ---------------- BN prep ----------------
__global__ void k_bnprep(const float* __restrict__ gamma, const float* __restrict__ beta) {
    int j = threadIdx.x;
    float invN = 1.0f / (float)NN;
    float mu = g_stats[j] * invN;
    float var = fmaxf(g_stats[DD + j] * invN - mu * mu, 0.f);
    float s = gamma[j] * rsqrtf(var + BN_EPS);
    g_cs[j] = s;
    g_cb[j] = beta[j] - mu * s;
    g_stats[j] = 0.f;
    g_stats[DD + j] = 0.f;
}

// ---------------- finalize: mean pools + layer-2 BN affine ----------------
__global__ void k_finalize(float* __restrict__ out_gf) {
    int idx = blockIdx.x * blockDim.x + threadIdx.x;
    if (idx >= (GG + MM) * DD) return;
    int row = idx / DD, j = idx % DD;
    float cs = g_cs[j], cb = g_cb[j];
    float v;
    if (row < GG) {
        v = cs * g_gsum[row * DD + j] / fmaxf(g_gcnt[row], 1.0f) + cb;
        out_gf[row * DD + j] = v;
    } else {
        int mrow = row - GG + 1;  // drop motif segment 0
        v = cs * g_msum[mrow * DD + j] / fmaxf(g_mcnt[mrow], 1.0f) + cb;
    }
    g_headin[idx] = v;
}

// ---------------- fp32 tiled GEMM with f32x2 (head MLP) ----------------
__global__ void k_gemm(const float* __restrict__ X, const float* __restrict__ W,
                       const float* __restrict__ bias,
                       float* __restrict__ Y, int nrows, int K, int ncols, int do_relu) {
    extern __shared__ float sm[];
    float* Ws = sm;               // 128*128
    float* Xs = sm + 128 * 128;   // 64*128
    const int tid = threadIdx.x;
    const int tx = tid & 31;
    const int ty = tid >> 5;
    const int r0 = blockIdx.x * 64;
    const int c0 = blockIdx.y * 128;

    unsigned long long acc[8][2];
#pragma unroll
    for (int m = 0; m < 8; m++) acc[m][0] = acc[m][1] = 0ull;

    for (int kb = 0; kb < K; kb += 128) {
#pragma unroll
        for (int i = 0; i < 16; i++) {
            int f = tid + 256 * i;
            int r = f >> 5, c4 = f & 31;
            ((float4*)Ws)[f] = *(const float4*)&W[(size_t)(kb + r) * ncols + c0 + c4 * 4];
        }
#pragma unroll
        for (int i = 0; i < 8; i++) {
            int f = tid + 256 * i;
            int m = f >> 5, k4 = f & 31;
            int row = r0 + m;
            float4 v = make_float4(0.f, 0.f, 0.f, 0.f);
            if (row < nrows) v = *(const float4*)&X[(size_t)row * K + kb + k4 * 4];
            ((float4*)Xs)[f] = v;
        }
        __syncthreads();

#pragma unroll 2
        for (int k = 0; k < 128; k += 4) {
            float4 xv[8];
#pragma unroll
            for (int m = 0; m < 8; m++)
                xv[m] = *(const float4*)&Xs[(ty * 8 + m) * 128 + k];
#pragma unroll
            for (int kk = 0; kk < 4; kk++) {
                ulonglong2 w = *(const ulonglong2*)&Ws[(k + kk) * 128 + tx * 4];
#pragma unroll
                for (int m = 0; m < 8; m++) {
                    float x = (kk == 0) ? xv[m].x : (kk == 1) ? xv[m].y
                            : (kk == 2) ? xv[m].z : xv[m].w;
                    unsigned long long xp = pack_dup(x);
                    ffma2(acc[m][0], xp, w.x);
                    ffma2(acc[m][1], xp, w.y);
                }
            }
        }
        __syncthreads();
    }

    float4 b4 = make_float4(0.f, 0.f, 0.f, 0.f);
    if (bias) b4 = *(const float4*)&bias[c0 + tx * 4];
#pragma unroll
    for (int m = 0; m < 8; m++) {
        int row = r0 + ty * 8 + m;
        if (row < nrows) {
            float2 p0 = unpack2(acc[m][0]);
            float2 p1 = unpack2(acc[m][1]);
            float4 o;
            o.x = p0.x + b4.x; o.y = p0.y + b4.y;
            o.z = p1.x + b4.z; o.w = p1.y + b4.w;
            if (do_relu) {
                o.x = fmaxf(o.x, 0.f); o.y = fmaxf(o.y, 0.f);
                o.z = fmaxf(o.z, 0.f); o.w = fmaxf(o.w, 0.f);
            }
            *(float4*)&Y[(size_t)row * ncols + c0 + tx * 4] = o;
        }
    }
}

// ---------------- launch ----------------
extern "C" void kernel_launch(void* const* d_in, const int* in_sizes, int n_in,
                              void* d_out, int out_size) {
    const float* node_feats = (const float*)d_in[0];
    const int*   src        = (const int*)d_in[1];
    const int*   dst        = (const int*)d_in[2];
    const int*   gid        = (const int*)d_in[3];
    const int*   mid        = (const int*)d_in[4];
    const float* Wg         = (const float*)d_in[5];
    const float* bg         = (const float*)d_in[6];
    const float* Wr         = (const float*)d_in[7];
    const float* br         = (const float*)d_in[8];
    const float* gamma      = (const float*)d_in[9];
    const float* beta       = (const float*)d_in[10];
    const float* W_feat     = (const float*)d_in[11];
    const float* b_feat     = (const float*)d_in[12];
    const float* W1         = (const float*)d_in[13];
    const float* b1         = (const float*)d_in[14];
    const float* W2         = (const float*)d_in[15];
    const float* b2         = (const float*)d_in[16];
    float* out = (float*)d_out;

    void *pA, *pns, *pcs, *pcb, *phin, *ph1, *ph2, *pB, *pR;
    cudaGetSymbolAddress(&pA, g_bufA);
    cudaGetSymbolAddress(&pB, g_bufB);
    cudaGetSymbolAddress(&pR, g_bufR);
    cudaGetSymbolAddress(&pns, g_norm_src);
    cudaGetSymbolAddress(&pcs, g_cs);
    cudaGetSymbolAddress(&pcb, g_cb);
    cudaGetSymbolAddress(&phin, g_headin);
    cudaGetSymbolAddress(&ph1, g_head1);
    cudaGetSymbolAddress(&ph2, g_head2);

    const int SMEM_G = (128 * 128 + 64 * 128) * 4;            // 96 KB (head gemm)
    const int SMEM_D = (3 * 128 * 64) * 4;                    // 96 KB (dual gemm, 2 CTAs/SM)
    cudaFuncSetAttribute(k_gemm, cudaFuncAttributeMaxDynamicSharedMemorySize, SMEM_G);
    cudaFuncSetAttribute(k_dualgemm, cudaFuncAttributeMaxDynamicSharedMemorySize, SMEM_D);

    const int agg_blocks = (NN + 7) / 8;      // 6250

    // ---- setup: degree histogram + norms (3 launches) ----
    k_zero<<<(NN + 255) / 256, 256>>>();
    k_hist<<<(EE + 255) / 256, 256>>>(src, dst);
    k_norms<<<(NN + 255) / 256, 256>>>();

    // ---- layer-0 dual GEMM as 4th launch (captured by ncu) ----
    k_dualgemm<<<dim3(148, 2), 256, SMEM_D>>>(
        node_feats, Wg, Wr, br, (const float*)pns,
        nullptr, nullptr, (float*)pB, (float*)pR, NN);

    // ---- CSR build (stream-ordered before k_agg) ----
    k_scan1<<<SCAN_B, 256>>>();
    k_scan2<<<1, 256>>>();
    k_scan3<<<SCAN_B, 256>>>();
    k_place<<<(EE + 255) / 256, 256>>>(src, dst);

    for (int l = 0; l < LL; l++) {
        if (l > 0) {
            k_dualgemm<<<dim3(148, 2), 256, SMEM_D>>>(
                (const float*)pA, Wg + (size_t)l * DD * DD, Wr + (size_t)l * DD * DD,
                br + (size_t)l * DD, (const float*)pns,
                (const float*)pcs, (const float*)pcb,
                (float*)pB, (float*)pR, NN);
        }

        // y = relu(agg*nd + bg) + R; BN stats accumulated.
        // l==0 zeroes pool buffers; l==2 accumulates raw-y pools (and skips bufA store).
        k_agg<<<agg_blocks, 256>>>(bg + (size_t)l * DD,
                                   (l == 0) ? 1 : 0,
                                   (l == LL - 1) ? 1 : 0,
                                   gid, mid);

        // fold BN into affine cs/cb; resets stats
        k_bnprep<<<1, DD>>>(gamma + (size_t)l * DD, beta + (size_t)l * DD);
    }

    // ---- finalize: mean pools + layer-2 BN affine -> out_gf and head input ----
    k_finalize<<<((GG + MM) * DD + 255) / 256, 256>>>(out);

    // ---- head MLP on [graph_feats ; h_sub] = 2560 rows ----
    const int HR = GG + MM;
    const int hblocks = (HR + 63) / 64;  // 40
    k_gemm<<<dim3(hblocks, FFN / 128), 256, SMEM_G>>>(
        (const float*)phin, W_feat, b_feat, (float*)ph1, HR, DD, FFN, 0);
    k_gemm<<<dim3(hblocks, FFN / 128), 256, SMEM_G>>>(
        (const float*)ph1, W1, b1, (float*)ph2, HR, FFN, FFN, 1);
    k_gemm<<<dim3(hblocks, 1), 256, SMEM_G>>>(
        (const float*)ph2, W2, b2, out + (size_t)GG * DD, HR, FFN, DD, 0);
}

// round 10
// speedup vs baseline: 1.0795x; 1.0368x over previous
#include <cuda_runtime.h>
#include <cuda_bf16.h>
#include <cstddef>

#define NN 50000
#define EE 600000
#define GG 512
#define MM 2048
#define DD 128
#define FFN 256
#define LL 3
#define BN_EPS 1e-5f
#define SCAN_B 196   // ceil(NN/256)

// ---------------- scratch (device globals) ----------------
__device__ float g_bufA[NN * DD];   // layer output h (raw, pre-BN)
__device__ float g_bufB[NN * DD];   // hw branch
__device__ float g_bufR[NN * DD];   // residual branch
__device__ int   g_degin[NN];
__device__ int   g_degout[NN];
__device__ int   g_cursor[NN];
__device__ int   g_rowstart[NN + 1];
__device__ int   g_csr_src[EE];
__device__ int   g_bsum[SCAN_B];
__device__ int   g_boff[SCAN_B];
__device__ float g_norm_src[NN];
__device__ float g_norm_dst[NN];
__device__ float g_stats[2 * DD];
__device__ float g_cs[DD];
__device__ float g_cb[DD];
__device__ float g_zero[DD];
__device__ float g_wp1[DD * DD];    // cs-scaled Wg[l]
__device__ float g_wp2[DD * DD];    // cs-scaled Wr[l]
__device__ float g_bc1[DD];         // cb @ Wg[l]
__device__ float g_bc2[DD];         // cb @ Wr[l] + br[l]
__device__ float g_gsum[GG * DD];
__device__ float g_gcnt[GG];
__device__ float g_msum[(MM + 1) * DD];
__device__ float g_mcnt[MM + 1];
__device__ float g_headin[(GG + MM) * DD];
__device__ float g_head1[(GG + MM) * FFN];
__device__ float g_head2[(GG + MM) * FFN];

// ---------------- f32x2 / cp.async helpers ----------------
__device__ __forceinline__ unsigned long long pack_dup(float x) {
    unsigned long long p;
    unsigned int xb = __float_as_uint(x);
    asm("mov.b64 %0, {%1, %1};" : "=l"(p) : "r"(xb));
    return p;
}
__device__ __forceinline__ void ffma2(unsigned long long& acc, unsigned long long a,
                                      unsigned long long b) {
    asm("fma.rn.f32x2 %0, %1, %2, %0;" : "+l"(acc) : "l"(a), "l"(b));
}
__device__ __forceinline__ float2 unpack2(unsigned long long a) {
    float lo, hi;
    asm("mov.b64 {%0, %1}, %2;" : "=f"(lo), "=f"(hi) : "l"(a));
    return make_float2(lo, hi);
}
__device__ __forceinline__ void cp_async16(unsigned smem_addr, const void* gptr, bool valid) {
    int sz = valid ? 16 : 0;   // zfill when out of range
    asm volatile("cp.async.cg.shared.global [%0], [%1], 16, %2;\n"
                 :: "r"(smem_addr), "l"(gptr), "r"(sz));
}

// ---------------- setup ----------------
__global__ void k_zero() {
    int i = blockIdx.x * blockDim.x + threadIdx.x;
    if (i < NN) { g_degin[i] = 0; g_degout[i] = 0; }
}

__global__ void k_hist(const int* __restrict__ src, const int* __restrict__ dst) {
    int e = blockIdx.x * blockDim.x + threadIdx.x;
    if (e < EE) {
        atomicAdd(&g_degout[src[e]], 1);
        atomicAdd(&g_degin[dst[e]], 1);
    }
}

__global__ void k_norms() {
    int i = blockIdx.x * blockDim.x + threadIdx.x;
    if (i < NN) {
        g_norm_src[i] = rsqrtf(fmaxf((float)g_degout[i], 1.0f));
        g_norm_dst[i] = rsqrtf(fmaxf((float)g_degin[i], 1.0f));
    }
    if (i < 2 * DD) g_stats[i] = 0.f;
    if (i < DD) g_zero[i] = 0.f;
}

// ---------------- multi-block scan of g_degin -> g_rowstart ----------------
__global__ void k_scan1() {
    __shared__ int sh[256];
    int tid = threadIdx.x;
    int i = blockIdx.x * 256 + tid;
    int v = (i < NN) ? g_degin[i] : 0;
    if (i < NN) g_cursor[i] = 0;
    sh[tid] = v;
    __syncthreads();
    for (int off = 128; off > 0; off >>= 1) {
        if (tid < off) sh[tid] += sh[tid + off];
        __syncthreads();
    }
    if (tid == 0) g_bsum[blockIdx.x] = sh[0];
}

__global__ void k_scan2() {
    __shared__ int sh[256];
    int tid = threadIdx.x;
    int v = (tid < SCAN_B) ? g_bsum[tid] : 0;
    sh[tid] = v;
    __syncthreads();
    for (int off = 1; off < 256; off <<= 1) {
        int t = (tid >= off) ? sh[tid - off] : 0;
        __syncthreads();
        sh[tid] += t;
        __syncthreads();
    }
    if (tid < SCAN_B) g_boff[tid] = sh[tid] - v;
}

__global__ void k_scan3() {
    __shared__ int sh[256];
    int tid = threadIdx.x;
    int i = blockIdx.x * 256 + tid;
    int v = (i < NN) ? g_degin[i] : 0;
    sh[tid] = v;
    __syncthreads();
    for (int off = 1; off < 256; off <<= 1) {
        int t = (tid >= off) ? sh[tid - off] : 0;
        __syncthreads();
        sh[tid] += t;
        __syncthreads();
    }
    if (i < NN) g_rowstart[i] = sh[tid] - v + g_boff[blockIdx.x];
    if (blockIdx.x == 0 && tid == 0) g_rowstart[NN] = EE;
}

__global__ void k_place(const int* __restrict__ src, const int* __restrict__ dst) {
    int e = blockIdx.x * blockDim.x + threadIdx.x;
    if (e < EE) {
        int d = dst[e];
        int slot = atomicAdd(&g_cursor[d], 1);
        g_csr_src[g_rowstart[d] + slot] = src[e];
    }
}

// ---------------- BN-affine weight prep (layers 1,2) ----------------
// wp = diag(cs) @ W ;  bc1 = cb @ W1 ;  bc2 = cb @ W2 + br
__global__ void k_wprep(const float* __restrict__ W1, const float* __restrict__ W2) {
    int k = blockIdx.x, c = threadIdx.x;
    float s = g_cs[k];
    g_wp1[k * DD + c] = s * W1[k * DD + c];
    g_wp2[k * DD + c] = s * W2[k * DD + c];
}

__global__ void k_wbias(const float* __restrict__ W1, const float* __restrict__ W2,
                        const float* __restrict__ br) {
    int tid = threadIdx.x;   // 256
    int c = tid & (DD - 1);
    const float* W = (tid < DD) ? W1 : W2;
    float s = 0.f;
#pragma unroll 4
    for (int k = 0; k < DD; k++) s += g_cb[k] * W[k * DD + c];
    if (tid < DD) g_bc1[c] = s;
    else          g_bc2[c] = s + br[c];
}

// ---------------- fused dual GEMM: cp.async double-buffered, fp32 FFMA2 ----------------
// Y1 = rs .* (X @ W1 + b1c)      (weights pre-scaled by BN affine; b1c = cb@W1)
// Y2 = relu(X @ W2 + b2c)        (b2c = cb@W2 + br)
// 128-row x 64-col tile, K chunked by 32, 2 smem X buffers. 96 KB -> 2 CTAs/SM.
__global__ void __launch_bounds__(256, 2)
k_dualgemm(const float* __restrict__ X,
           const float* __restrict__ W1,
           const float* __restrict__ W2,
           const float* __restrict__ b1c,
           const float* __restrict__ b2c,
           const float* __restrict__ rs,
           float* __restrict__ Y1, float* __restrict__ Y2,
           int nrows) {
    extern __shared__ float sm[];
    float* Xs  = sm;               // 2 x (128*32) floats = 32 KB
    float* W1s = sm + 2 * 128 * 32;  // 128*64 = 32 KB
    float* W2s = W1s + 128 * 64;     // 32 KB
    const int tid = threadIdx.x;
    const int tx = tid & 15;       // 16 col-groups of 4 cols
    const int ty = tid >> 4;       // 16 row-groups of 8 rows
    const int r0 = blockIdx.x * 128;
    const int c0 = blockIdx.y * 64;

    // W tiles resident: 2048 float4 each; 8 per thread
#pragma unroll
    for (int i = 0; i < 8; i++) {
        int f = tid + 256 * i;
        int r = f >> 4, c4 = f & 15;
        ((float4*)W1s)[f] = ((const float4*)&W1[(size_t)r * DD + c0])[c4];
        ((float4*)W2s)[f] = ((const float4*)&W2[(size_t)r * DD + c0])[c4];
    }

    // async-load helper: chunk kc (K cols [kc*32, kc*32+32)) into buffer buf
    unsigned xs_base = (unsigned)__cvta_generic_to_shared(Xs);
#define LD_CHUNK(kc, bufsel) do {                                            \
        unsigned base = xs_base + (bufsel) * 128 * 32 * 4;                   \
        _Pragma("unroll")                                                    \
        for (int i = 0; i < 4; i++) {                                        \
            int f = tid + 256 * i;          /* 1024 float4 */                \
            int rl = f >> 3, j4 = f & 7;    /* 8 float4 per row */           \
            int row = r0 + rl;                                               \
            cp_async16(base + (unsigned)(rl * 32 + j4 * 4) * 4,              \
                       X + (size_t)row * DD + (kc) * 32 + j4 * 4,            \
                       row < nrows);                                         \
        }                                                                    \
        asm volatile("cp.async.commit_group;");                              \
    } while (0)

    unsigned long long a1[8][2], a2[8][2];
#pragma unroll
    for (int m = 0; m < 8; m++) {
        a1[m][0] = a1[m][1] = 0ull;
        a2[m][0] = a2[m][1] = 0ull;
    }

    LD_CHUNK(0, 0);
#pragma unroll
    for (int kc = 0; kc < 4; kc++) {
        if (kc < 3) {
            LD_CHUNK(kc + 1, (kc + 1) & 1);
            asm volatile("cp.async.wait_group 1;");
        } else {
            asm volatile("cp.async.wait_group 0;");
        }
        __syncthreads();   // chunk kc visible to all; also drains prior readers

        const float* buf = Xs + (kc & 1) * 128 * 32;
#pragma unroll
        for (int k = 0; k < 32; k += 4) {
            float4 xv[8];
#pragma unroll
            for (int m = 0; m < 8; m++)
                xv[m] = *(const float4*)&buf[(ty * 8 + m) * 32 + k];
#pragma unroll
            for (int kk = 0; kk < 4; kk++) {
                int kg = kc * 32 + k + kk;
                ulonglong2 w1 = *(const ulonglong2*)&W1s[kg * 64 + tx * 4];
                ulonglong2 w2 = *(const ulonglong2*)&W2s[kg * 64 + tx * 4];
#pragma unroll
                for (int m = 0; m < 8; m++) {
                    float x = (kk == 0) ? xv[m].x : (kk == 1) ? xv[m].y
                            : (kk == 2) ? xv[m].z : xv[m].w;
                    unsigned long long xp = pack_dup(x);
                    ffma2(a1[m][0], xp, w1.x);
                    ffma2(a1[m][1], xp, w1.y);
                    ffma2(a2[m][0], xp, w2.x);
                    ffma2(a2[m][1], xp, w2.y);
                }
            }
        }
        __syncthreads();   // done reading buf before it is overwritten
    }
#undef LD_CHUNK

    float4 c1v = ((const float4*)&b1c[c0])[tx];
    float4 c2v = ((const float4*)&b2c[c0])[tx];
#pragma unroll
    for (int m = 0; m < 8; m++) {
        int row = r0 + ty * 8 + m;
        if (row < nrows) {
            float s = rs[row];
            float2 p0 = unpack2(a1[m][0]);
            float2 p1 = unpack2(a1[m][1]);
            float4 o1;
            o1.x = (p0.x + c1v.x) * s; o1.y = (p0.y + c1v.y) * s;
            o1.z = (p1.x + c1v.z) * s; o1.w = (p1.y + c1v.w) * s;
            ((float4*)(Y1 + (size_t)row * DD + c0))[tx] = o1;
            float2 q0 = unpack2(a2[m][0]);
            float2 q1 = unpack2(a2[m][1]);
            float4 o2;
            o2.x = fmaxf(q0.x + c2v.x, 0.f);
            o2.y = fmaxf(q0.y + c2v.y, 0.f);
            o2.z = fmaxf(q1.x + c2v.z, 0.f);
            o2.w = fmaxf(q1.y + c2v.w, 0.f);
            ((float4*)(Y2 + (size_t)row * DD + c0))[tx] = o2;
        }
    }
}

// ---------------- CSR aggregation + combine + BN stats (+ pooling on last layer) ----------------
__global__ void k_agg(const float* __restrict__ bg, int zpool, int do_pool,
                      const int* __restrict__ gid, const int* __restrict__ mid) {
    __shared__ float ssum[8][DD];
    __shared__ float ssq[8][DD];
    int tid = threadIdx.x;
    int w = tid >> 5;
    int lane = tid & 31;

    if (zpool) {
        int gstep = gridDim.x * blockDim.x;
        int gidx = blockIdx.x * blockDim.x + tid;
        for (int i = gidx; i < GG * DD; i += gstep) g_gsum[i] = 0.f;
        for (int i = gidx; i < (MM + 1) * DD; i += gstep) g_msum[i] = 0.f;
        for (int i = gidx; i < GG; i += gstep) g_gcnt[i] = 0.f;
        for (int i = gidx; i < MM + 1; i += gstep) g_mcnt[i] = 0.f;
    }

    int node = blockIdx.x * 8 + w;
    float4 y = make_float4(0.f, 0.f, 0.f, 0.f);
    if (node < NN) {
        int e0 = g_rowstart[node], e1 = g_rowstart[node + 1];
        float4 acc[8];
#pragma unroll
        for (int i = 0; i < 8; i++) acc[i] = make_float4(0.f, 0.f, 0.f, 0.f);
        int e = e0;
        for (; e + 8 <= e1; e += 8) {
            float4 v[8];
#pragma unroll
            for (int i = 0; i < 8; i++) {
                int s = g_csr_src[e + i];
                v[i] = ((const float4*)(g_bufB + (size_t)s * DD))[lane];
            }
#pragma unroll
            for (int i = 0; i < 8; i++) {
                acc[i].x += v[i].x; acc[i].y += v[i].y;
                acc[i].z += v[i].z; acc[i].w += v[i].w;
            }
        }
        if (e + 4 <= e1) {
            float4 v[4];
#pragma unroll
            for (int i = 0; i < 4; i++) {
                int s = g_csr_src[e + i];
                v[i] = ((const float4*)(g_bufB + (size_t)s * DD))[lane];
            }
#pragma unroll
            for (int i = 0; i < 4; i++) {
                acc[i].x += v[i].x; acc[i].y += v[i].y;
                acc[i].z += v[i].z; acc[i].w += v[i].w;
            }
            e += 4;
        }
        for (; e < e1; e++) {
            int s = g_csr_src[e];
            float4 v0 = ((const float4*)(g_bufB + (size_t)s * DD))[lane];
            acc[0].x += v0.x; acc[0].y += v0.y; acc[0].z += v0.z; acc[0].w += v0.w;
        }
#pragma unroll
        for (int i = 4; i < 8; i++) {
            acc[i - 4].x += acc[i].x; acc[i - 4].y += acc[i].y;
            acc[i - 4].z += acc[i].z; acc[i - 4].w += acc[i].w;
        }
        acc[0].x += acc[2].x + acc[1].x + acc[3].x;
        acc[0].y += acc[2].y + acc[1].y + acc[3].y;
        acc[0].z += acc[2].z + acc[1].z + acc[3].z;
        acc[0].w += acc[2].w + acc[1].w + acc[3].w;

        float nd = g_norm_dst[node];
        float4 b4 = ((const float4*)bg)[lane];
        float4 r = ((const float4*)(g_bufR + (size_t)node * DD))[lane];
        y.x = fmaxf(fmaf(acc[0].x, nd, b4.x), 0.f) + r.x;
        y.y = fmaxf(fmaf(acc[0].y, nd, b4.y), 0.f) + r.y;
        y.z = fmaxf(fmaf(acc[0].z, nd, b4.z), 0.f) + r.z;
        y.w = fmaxf(fmaf(acc[0].w, nd, b4.w), 0.f) + r.w;

        if (do_pool) {
            int gi = gid[node], mi = mid[node];
            atomicAdd(((float4*)(g_gsum + (size_t)gi * DD)) + lane, y);
            atomicAdd(((float4*)(g_msum + (size_t)mi * DD)) + lane, y);
            if (lane == 0) {
                atomicAdd(&g_gcnt[gi], 1.0f);
                atomicAdd(&g_mcnt[mi], 1.0f);
            }
        } else {
            ((float4*)(g_bufA + (size_t)node * DD))[lane] = y;
        }
    }
    ((float4*)&ssum[w][0])[lane] = y;
    float4 y2 = make_float4(y.x * y.x, y.y * y.y, y.z * y.z, y.w * y.w);
    ((float4*)&ssq[w][0])[lane] = y2;
    __syncthreads();
    if (tid < DD) {
        float s = 0.f;
#pragma unroll
        for (int i = 0; i < 8; i++) s += ssum[i][tid];
        atomicAdd(&g_stats[tid], s);
    } else {
        int j = tid - DD;
        float s = 0.f;
#pragma unroll
        for (int i = 0; i < 8; i++) s += ssq[i][j];
        atomicAdd(&g_stats[DD + j], s);
    }
}

// ---------------- BN prep ----------------
__global__ void k_bnprep(const float* __restrict__ gamma, const float* __restrict__ beta) {
    int j = threadIdx.x;
    float invN = 1.0f / (float)NN;
    float mu = g_stats[j] * invN;
    float var = fmaxf(g_stats[DD + j] * invN - mu * mu, 0.f);
    float s = gamma[j] * rsqrtf(var + BN_EPS);
    g_cs[j] = s;
    g_cb[j] = beta[j] - mu * s;
    g_stats[j] = 0.f;
    g_stats[DD + j] = 0.f;
}

// ---------------- finalize: mean pools + layer-2 BN affine ----------------
__global__ void k_finalize(float* __restrict__ out_gf) {
    int idx = blockIdx.x * blockDim.x + threadIdx.x;
    if (idx >= (GG + MM) * DD) return;
    int row = idx / DD, j = idx % DD;
    float cs = g_cs[j], cb = g_cb[j];
    float v;
    if (row < GG) {
        v = cs * g_gsum[row * DD + j] / fmaxf(g_gcnt[row], 1.0f) + cb;
        out_gf[row * DD + j] = v;
    } else {
        int mrow = row - GG + 1;
        v = cs * g_msum[mrow * DD + j] / fmaxf(g_mcnt[mrow], 1.0f) + cb;
    }
    g_headin[idx] = v;
}

// ---------------- fp32 tiled GEMM with f32x2 (head MLP) ----------------
__global__ void k_gemm(const float* __restrict__ X, const float* __restrict__ W,
                       const float* __restrict__ bias,
                       float* __restrict__ Y, int nrows, int K, int ncols, int do_relu) {
    extern __shared__ float sm[];
    float* Ws = sm;
    float* Xs = sm + 128 * 128;
    const int tid = threadIdx.x;
    const int tx = tid & 31;
    const int ty = tid >> 5;
    const int r0 = blockIdx.x * 64;
    const int c0 = blockIdx.y * 128;

    unsigned long long acc[8][2];
#pragma unroll
    for (int m = 0; m < 8; m++) acc[m][0] = acc[m][1] = 0ull;

    for (int kb = 0; kb < K; kb += 128) {
#pragma unroll
        for (int i = 0; i < 16; i++) {
            int f = tid + 256 * i;
            int r = f >> 5, c4 = f & 31;
            ((float4*)Ws)[f] = *(const float4*)&W[(size_t)(kb + r) * ncols + c0 + c4 * 4];
        }
#pragma unroll
        for (int i = 0; i < 8; i++) {
            int f = tid + 256 * i;
            int m = f >> 5, k4 = f & 31;
            int row = r0 + m;
            float4 v = make_float4(0.f, 0.f, 0.f, 0.f);
            if (row < nrows) v = *(const float4*)&X[(size_t)row * K + kb + k4 * 4];
            ((float4*)Xs)[f] = v;
        }
        __syncthreads();

#pragma unroll 2
        for (int k = 0; k < 128; k += 4) {
            float4 xv[8];
#pragma unroll
            for (int m = 0; m < 8; m++)
                xv[m] = *(const float4*)&Xs[(ty * 8 + m) * 128 + k];
#pragma unroll
            for (int kk = 0; kk < 4; kk++) {
                ulonglong2 w = *(const ulonglong2*)&Ws[(k + kk) * 128 + tx * 4];
#pragma unroll
                for (int m = 0; m < 8; m++) {
                    float x = (kk == 0) ? xv[m].x : (kk == 1) ? xv[m].y
                            : (kk == 2) ? xv[m].z : xv[m].w;
                    unsigned long long xp = pack_dup(x);
                    ffma2(acc[m][0], xp, w.x);
                    ffma2(acc[m][1], xp, w.y);
                }
            }
        }
        __syncthreads();
    }

    float4 b4 = make_float4(0.f, 0.f, 0.f, 0.f);
    if (bias) b4 = *(const float4*)&bias[c0 + tx * 4];
#pragma unroll
    for (int m = 0; m < 8; m++) {
        int row = r0 + ty * 8 + m;
        if (row < nrows) {
            float2 p0 = unpack2(acc[m][0]);
            float2 p1 = unpack2(acc[m][1]);
            float4 o;
            o.x = p0.x + b4.x; o.y = p0.y + b4.y;
            o.z = p1.x + b4.z; o.w = p1.y + b4.w;
            if (do_relu) {
                o.x = fmaxf(o.x, 0.f); o.y = fmaxf(o.y, 0.f);
                o.z = fmaxf(o.z, 0.f); o.w = fmaxf(o.w, 0.f);
            }
            *(float4*)&Y[(size_t)row * ncols + c0 + tx * 4] = o;
        }
    }
}

// ---------------- launch ----------------
extern "C" void kernel_launch(void* const* d_in, const int* in_sizes, int n_in,
                              void* d_out, int out_size) {
    const float* node_feats = (const float*)d_in[0];
    const int*   src        = (const int*)d_in[1];
    const int*   dst        = (const int*)d_in[2];
    const int*   gid        = (const int*)d_in[3];
    const int*   mid        = (const int*)d_in[4];
    const float* Wg         = (const float*)d_in[5];
    const float* bg         = (const float*)d_in[6];
    const float* Wr         = (const float*)d_in[7];
    const float* br         = (const float*)d_in[8];
    const float* gamma      = (const float*)d_in[9];
    const float* beta       = (const float*)d_in[10];
    const float* W_feat     = (const float*)d_in[11];
    const float* b_feat     = (const float*)d_in[12];
    const float* W1         = (const float*)d_in[13];
    const float* b1         = (const float*)d_in[14];
    const float* W2         = (const float*)d_in[15];
    const float* b2         = (const float*)d_in[16];
    float* out = (float*)d_out;

    void *pA, *pns, *phin, *ph1, *ph2, *pB, *pR, *pwp1, *pwp2, *pbc1, *pbc2, *pz;
    cudaGetSymbolAddress(&pA, g_bufA);
    cudaGetSymbolAddress(&pB, g_bufB);
    cudaGetSymbolAddress(&pR, g_bufR);
    cudaGetSymbolAddress(&pns, g_norm_src);
    cudaGetSymbolAddress(&phin, g_headin);
    cudaGetSymbolAddress(&ph1, g_head1);
    cudaGetSymbolAddress(&ph2, g_head2);
    cudaGetSymbolAddress(&pwp1, g_wp1);
    cudaGetSymbolAddress(&pwp2, g_wp2);
    cudaGetSymbolAddress(&pbc1, g_bc1);
    cudaGetSymbolAddress(&pbc2, g_bc2);
    cudaGetSymbolAddress(&pz, g_zero);

    const int SMEM_G = (128 * 128 + 64 * 128) * 4;   // 96 KB (head gemm)
    const int SMEM_D = (2 * 128 * 32 + 2 * 128 * 64) * 4;  // 96 KB (dual gemm, 2 CTAs/SM)
    cudaFuncSetAttribute(k_gemm, cudaFuncAttributeMaxDynamicSharedMemorySize, SMEM_G);
    cudaFuncSetAttribute(k_dualgemm, cudaFuncAttributeMaxDynamicSharedMemorySize, SMEM_D);

    const int gemm_rows = (NN + 127) / 128;   // 391
    const int agg_blocks = (NN + 7) / 8;      // 6250

    // ---- setup ----
    k_zero<<<(NN + 255) / 256, 256>>>();
    k_hist<<<(EE + 255) / 256, 256>>>(src, dst);
    k_norms<<<(NN + 255) / 256, 256>>>();

    // ---- layer-0 dual GEMM (4th launch, ncu-captured): raw weights, b1c=0, b2c=br ----
    k_dualgemm<<<dim3(gemm_rows, 2), 256, SMEM_D>>>(
        node_feats, Wg, Wr, (const float*)pz, br, (const float*)pns,
        (float*)pB, (float*)pR, NN);

    // ---- CSR build (stream-ordered before k_agg) ----
    k_scan1<<<SCAN_B, 256>>>();
    k_scan2<<<1, 256>>>();
    k_scan3<<<SCAN_B, 256>>>();
    k_place<<<(EE + 255) / 256, 256>>>(src, dst);

    for (int l = 0; l < LL; l++) {
        if (l > 0) {
            // fold BN affine (from previous layer's bnprep) into weights/biases
            k_wprep<<<DD, DD>>>(Wg + (size_t)l * DD * DD, Wr + (size_t)l * DD * DD);
            k_wbias<<<1, 2 * DD>>>(Wg + (size_t)l * DD * DD, Wr + (size_t)l * DD * DD,
                                   br + (size_t)l * DD);
            k_dualgemm<<<dim3(gemm_rows, 2), 256, SMEM_D>>>(
                (const float*)pA, (const float*)pwp1, (const float*)pwp2,
                (const float*)pbc1, (const float*)pbc2, (const float*)pns,
                (float*)pB, (float*)pR, NN);
        }

        k_agg<<<agg_blocks, 256>>>(bg + (size_t)l * DD,
                                   (l == 0) ? 1 : 0,
                                   (l == LL - 1) ? 1 : 0,
                                   gid, mid);

        k_bnprep<<<1, DD>>>(gamma + (size_t)l * DD, beta + (size_t)l * DD);
    }

    // ---- finalize: mean pools + layer-2 BN affine ----
    k_finalize<<<((GG + MM) * DD + 255) / 256, 256>>>(out);

    // ---- head MLP on [graph_feats ; h_sub] = 2560 rows ----
    const int HR = GG + MM;
    const int hblocks = (HR + 63) / 64;
    k_gemm<<<dim3(hblocks, FFN / 128), 256, SMEM_G>>>(
        (const float*)phin, W_feat, b_feat, (float*)ph1, HR, DD, FFN, 0);
    k_gemm<<<dim3(hblocks, FFN / 128), 256, SMEM_G>>>(
        (const float*)ph1, W1, b1, (float*)ph2, HR, FFN, FFN, 1);
    k_gemm<<<dim3(hblocks, 1), 256, SMEM_G>>>(
        (const float*)ph2, W2, b2, out + (size_t)GG * DD, HR, FFN, DD, 0);
}

// round 11
// speedup vs baseline: 1.1773x; 1.0906x over previous
#include <cuda_runtime.h>
#include <cuda_bf16.h>
#include <mma.h>
#include <cstddef>

using namespace nvcuda;

#define NN 50000
#define EE 600000
#define GG 512
#define MM 2048
#define DD 128
#define FFN 256
#define LL 3
#define BN_EPS 1e-5f
#define SCAN_B 196   // ceil(NN/256)
#define LDP 72       // padded bf16 row length (144B) -> conflict-free ldmatrix

// ---------------- scratch (device globals) ----------------
__device__ float g_bufA[NN * DD];   // layer output h (raw, pre-BN)
__device__ float g_bufB[NN * DD];   // hw branch
__device__ float g_bufR[NN * DD];   // residual branch
__device__ int   g_degin[NN];
__device__ int   g_degout[NN];
__device__ int   g_cursor[NN];
__device__ int   g_rowstart[NN + 1];
__device__ int   g_csr_src[EE];
__device__ int   g_bsum[SCAN_B];
__device__ int   g_boff[SCAN_B];
__device__ float g_norm_src[NN];
__device__ float g_norm_dst[NN];
__device__ float g_stats[2 * DD];
__device__ float g_cs[DD];
__device__ float g_cb[DD];
__device__ float g_zero[DD];
__device__ float g_wp1[DD * DD];    // cs-scaled Wg[l]
__device__ float g_wp2[DD * DD];    // cs-scaled Wr[l]
__device__ float g_bc1[DD];         // cb @ Wg[l]
__device__ float g_bc2[DD];         // cb @ Wr[l] + br[l]
__device__ float g_gsum[GG * DD];
__device__ float g_gcnt[GG];
__device__ float g_msum[(MM + 1) * DD];
__device__ float g_mcnt[MM + 1];
__device__ float g_headin[(GG + MM) * DD];
__device__ float g_head1[(GG + MM) * FFN];
__device__ float g_head2[(GG + MM) * FFN];

// ---------------- f32x2 helpers (head GEMM) ----------------
__device__ __forceinline__ unsigned long long pack_dup(float x) {
    unsigned long long p;
    unsigned int xb = __float_as_uint(x);
    asm("mov.b64 %0, {%1, %1};" : "=l"(p) : "r"(xb));
    return p;
}
__device__ __forceinline__ void ffma2(unsigned long long& acc, unsigned long long a,
                                      unsigned long long b) {
    asm("fma.rn.f32x2 %0, %1, %2, %0;" : "+l"(acc) : "l"(a), "l"(b));
}
__device__ __forceinline__ float2 unpack2(unsigned long long a) {
    float lo, hi;
    asm("mov.b64 {%0, %1}, %2;" : "=f"(lo), "=f"(hi) : "l"(a));
    return make_float2(lo, hi);
}

// ---------------- bf16 hi/lo split store (4 values) ----------------
__device__ __forceinline__ void split_store(__nv_bfloat16* ph, __nv_bfloat16* pl, float4 v) {
    __nv_bfloat162 h01 = __floats2bfloat162_rn(v.x, v.y);
    __nv_bfloat162 h23 = __floats2bfloat162_rn(v.z, v.w);
    float2 f01 = __bfloat1622float2(h01);
    float2 f23 = __bfloat1622float2(h23);
    __nv_bfloat162 l01 = __floats2bfloat162_rn(v.x - f01.x, v.y - f01.y);
    __nv_bfloat162 l23 = __floats2bfloat162_rn(v.z - f23.x, v.w - f23.y);
    uint2 hv, lv;
    hv.x = *(unsigned*)&h01; hv.y = *(unsigned*)&h23;
    lv.x = *(unsigned*)&l01; lv.y = *(unsigned*)&l23;
    *(uint2*)ph = hv;
    *(uint2*)pl = lv;
}

// ---------------- setup ----------------
__global__ void k_zero() {
    int i = blockIdx.x * blockDim.x + threadIdx.x;
    if (i < NN) { g_degin[i] = 0; g_degout[i] = 0; }
}

__global__ void k_hist(const int* __restrict__ src, const int* __restrict__ dst) {
    int e = blockIdx.x * blockDim.x + threadIdx.x;
    if (e < EE) {
        atomicAdd(&g_degout[src[e]], 1);
        atomicAdd(&g_degin[dst[e]], 1);
    }
}

__global__ void k_norms() {
    int i = blockIdx.x * blockDim.x + threadIdx.x;
    if (i < NN) {
        g_norm_src[i] = rsqrtf(fmaxf((float)g_degout[i], 1.0f));
        g_norm_dst[i] = rsqrtf(fmaxf((float)g_degin[i], 1.0f));
    }
    if (i < 2 * DD) g_stats[i] = 0.f;
    if (i < DD) g_zero[i] = 0.f;
}

// ---------------- multi-block scan of g_degin -> g_rowstart ----------------
__global__ void k_scan1() {
    __shared__ int sh[256];
    int tid = threadIdx.x;
    int i = blockIdx.x * 256 + tid;
    int v = (i < NN) ? g_degin[i] : 0;
    if (i < NN) g_cursor[i] = 0;
    sh[tid] = v;
    __syncthreads();
    for (int off = 128; off > 0; off >>= 1) {
        if (tid < off) sh[tid] += sh[tid + off];
        __syncthreads();
    }
    if (tid == 0) g_bsum[blockIdx.x] = sh[0];
}

__global__ void k_scan2() {
    __shared__ int sh[256];
    int tid = threadIdx.x;
    int v = (tid < SCAN_B) ? g_bsum[tid] : 0;
    sh[tid] = v;
    __syncthreads();
    for (int off = 1; off < 256; off <<= 1) {
        int t = (tid >= off) ? sh[tid - off] : 0;
        __syncthreads();
        sh[tid] += t;
        __syncthreads();
    }
    if (tid < SCAN_B) g_boff[tid] = sh[tid] - v;
}

__global__ void k_scan3() {
    __shared__ int sh[256];
    int tid = threadIdx.x;
    int i = blockIdx.x * 256 + tid;
    int v = (i < NN) ? g_degin[i] : 0;
    sh[tid] = v;
    __syncthreads();
    for (int off = 1; off < 256; off <<= 1) {
        int t = (tid >= off) ? sh[tid - off] : 0;
        __syncthreads();
        sh[tid] += t;
        __syncthreads();
    }
    if (i < NN) g_rowstart[i] = sh[tid] - v + g_boff[blockIdx.x];
    if (blockIdx.x == 0 && tid == 0) g_rowstart[NN] = EE;
}

__global__ void k_place(const int* __restrict__ src, const int* __restrict__ dst) {
    int e = blockIdx.x * blockDim.x + threadIdx.x;
    if (e < EE) {
        int d = dst[e];
        int slot = atomicAdd(&g_cursor[d], 1);
        g_csr_src[g_rowstart[d] + slot] = src[e];
    }
}

// ---------------- BN-affine weight prep (layers 1,2) ----------------
__global__ void k_wprep(const float* __restrict__ W1, const float* __restrict__ W2) {
    int k = blockIdx.x, c = threadIdx.x;
    float s = g_cs[k];
    g_wp1[k * DD + c] = s * W1[k * DD + c];
    g_wp2[k * DD + c] = s * W2[k * DD + c];
}

__global__ void k_wbias(const float* __restrict__ W1, const float* __restrict__ W2,
                        const float* __restrict__ br) {
    int tid = threadIdx.x;   // 256
    int c = tid & (DD - 1);
    const float* W = (tid < DD) ? W1 : W2;
    float s = 0.f;
#pragma unroll 4
    for (int k = 0; k < DD; k++) s += g_cb[k] * W[k * DD + c];
    if (tid < DD) g_bc1[c] = s;
    else          g_bc2[c] = s + br[c];
}

// ---------------- dual GEMM: split-bf16 tensor cores (3-term, ~fp32 accuracy) ----------------
// Y1 = rs .* (X @ W1 + b1c);  Y2 = relu(X @ W2 + b2c)
// Tile 128 rows x 64 cols; 8 warps (4m x 2n), each 32x32 out as 2x2 m16n16k16 frags.
// x = hi + lo (bf16 each); x@w ~= hi@whi + hi@wlo + lo@whi (products exact, fp32 acc).
__global__ void __launch_bounds__(256)
k_dualgemm(const float* __restrict__ X,
           const float* __restrict__ W1f,
           const float* __restrict__ W2f,
           const float* __restrict__ b1c,
           const float* __restrict__ b2c,
           const float* __restrict__ rs,
           float* __restrict__ Y1, float* __restrict__ Y2,
           int nrows) {
    extern __shared__ __nv_bfloat16 smb[];
    __nv_bfloat16* W1h = smb;                    // 128*LDP each (18 KB)
    __nv_bfloat16* W1l = W1h + 128 * LDP;
    __nv_bfloat16* W2h = W1l + 128 * LDP;
    __nv_bfloat16* W2l = W2h + 128 * LDP;
    __nv_bfloat16* Xh  = W2l + 128 * LDP;
    __nv_bfloat16* Xl  = Xh + 128 * LDP;         // total 6*18 KB = 108 KB
    float* stage = (float*)Xh;                   // 128*LDP floats == Xh+Xl bytes

    const int tid = threadIdx.x;
    const int w = tid >> 5;
    const int wr = (w & 3) * 32;
    const int wc = (w >> 2) * 32;
    const int r0 = blockIdx.x * 128;
    const int c0 = blockIdx.y * 64;

    // prefetch X chunk 0 (k 0..63) into registers
    float4 xreg[8];
#pragma unroll
    for (int i = 0; i < 8; i++) {
        int f = tid + 256 * i;
        int rl = f >> 4, j4 = f & 15;
        int row = r0 + rl;
        xreg[i] = make_float4(0.f, 0.f, 0.f, 0.f);
        if (row < nrows) xreg[i] = *(const float4*)&X[(size_t)row * DD + j4 * 4];
    }

    // convert W tiles (once): 128 k-rows x 64 cols, both matrices, hi/lo split
#pragma unroll
    for (int i = 0; i < 8; i++) {
        int f = tid + 256 * i;
        int k = f >> 4, c4 = f & 15;
        float4 v1 = ((const float4*)&W1f[(size_t)k * DD + c0])[c4];
        float4 v2 = ((const float4*)&W2f[(size_t)k * DD + c0])[c4];
        split_store(W1h + k * LDP + c4 * 4, W1l + k * LDP + c4 * 4, v1);
        split_store(W2h + k * LDP + c4 * 4, W2l + k * LDP + c4 * 4, v2);
    }

    wmma::fragment<wmma::accumulator, 16, 16, 16, float> acc1[2][2], acc2[2][2];
#pragma unroll
    for (int i = 0; i < 2; i++)
#pragma unroll
        for (int j = 0; j < 2; j++) {
            wmma::fill_fragment(acc1[i][j], 0.f);
            wmma::fill_fragment(acc2[i][j], 0.f);
        }

#pragma unroll 1
    for (int kc = 0; kc < 2; kc++) {
        __syncthreads();   // W stores visible (kc=0) / prior Xs readers done (kc=1)
#pragma unroll
        for (int i = 0; i < 8; i++) {
            int f = tid + 256 * i;
            int rl = f >> 4, j4 = f & 15;
            split_store(Xh + rl * LDP + j4 * 4, Xl + rl * LDP + j4 * 4, xreg[i]);
        }
        if (kc == 0) {
            // prefetch chunk 1 (k 64..127); latency hidden behind chunk-0 MMAs
#pragma unroll
            for (int i = 0; i < 8; i++) {
                int f = tid + 256 * i;
                int rl = f >> 4, j4 = f & 15;
                int row = r0 + rl;
                xreg[i] = make_float4(0.f, 0.f, 0.f, 0.f);
                if (row < nrows) xreg[i] = *(const float4*)&X[(size_t)row * DD + 64 + j4 * 4];
            }
        }
        __syncthreads();

#pragma unroll
        for (int ks = 0; ks < 64; ks += 16) {
            wmma::fragment<wmma::matrix_a, 16, 16, 16, __nv_bfloat16, wmma::row_major> ah[2], al[2];
#pragma unroll
            for (int i = 0; i < 2; i++) {
                wmma::load_matrix_sync(ah[i], Xh + (wr + 16 * i) * LDP + ks, LDP);
                wmma::load_matrix_sync(al[i], Xl + (wr + 16 * i) * LDP + ks, LDP);
            }
            int kg = kc * 64 + ks;
#pragma unroll
            for (int j = 0; j < 2; j++) {
                wmma::fragment<wmma::matrix_b, 16, 16, 16, __nv_bfloat16, wmma::row_major> bh, bl;
                wmma::load_matrix_sync(bh, W1h + kg * LDP + wc + 16 * j, LDP);
                wmma::load_matrix_sync(bl, W1l + kg * LDP + wc + 16 * j, LDP);
#pragma unroll
                for (int i = 0; i < 2; i++) {
                    wmma::mma_sync(acc1[i][j], ah[i], bh, acc1[i][j]);
                    wmma::mma_sync(acc1[i][j], ah[i], bl, acc1[i][j]);
                    wmma::mma_sync(acc1[i][j], al[i], bh, acc1[i][j]);
                }
                wmma::load_matrix_sync(bh, W2h + kg * LDP + wc + 16 * j, LDP);
                wmma::load_matrix_sync(bl, W2l + kg * LDP + wc + 16 * j, LDP);
#pragma unroll
                for (int i = 0; i < 2; i++) {
                    wmma::mma_sync(acc2[i][j], ah[i], bh, acc2[i][j]);
                    wmma::mma_sync(acc2[i][j], ah[i], bl, acc2[i][j]);
                    wmma::mma_sync(acc2[i][j], al[i], bh, acc2[i][j]);
                }
            }
        }
    }

    // ---- epilogue via fp32 staging (reuses X smem) ----
    __syncthreads();
#pragma unroll
    for (int i = 0; i < 2; i++)
#pragma unroll
        for (int j = 0; j < 2; j++)
            wmma::store_matrix_sync(stage + (wr + 16 * i) * LDP + wc + 16 * j,
                                    acc1[i][j], LDP, wmma::mem_row_major);
    __syncthreads();
#pragma unroll
    for (int i = 0; i < 8; i++) {
        int f = tid + 256 * i;
        int rl = f >> 4, c4 = f & 15;
        int row = r0 + rl;
        if (row < nrows) {
            float s = rs[row];
            float4 vv = *(const float4*)&stage[rl * LDP + c4 * 4];
            float4 bb = ((const float4*)&b1c[c0])[c4];
            float4 o;
            o.x = (vv.x + bb.x) * s; o.y = (vv.y + bb.y) * s;
            o.z = (vv.z + bb.z) * s; o.w = (vv.w + bb.w) * s;
            ((float4*)&Y1[(size_t)row * DD + c0])[c4] = o;
        }
    }
    __syncthreads();
#pragma unroll
    for (int i = 0; i < 2; i++)
#pragma unroll
        for (int j = 0; j < 2; j++)
            wmma::store_matrix_sync(stage + (wr + 16 * i) * LDP + wc + 16 * j,
                                    acc2[i][j], LDP, wmma::mem_row_major);
    __syncthreads();
#pragma unroll
    for (int i = 0; i < 8; i++) {
        int f = tid + 256 * i;
        int rl = f >> 4, c4 = f & 15;
        int row = r0 + rl;
        if (row < nrows) {
            float4 vv = *(const float4*)&stage[rl * LDP + c4 * 4];
            float4 bb = ((const float4*)&b2c[c0])[c4];
            float4 o;
            o.x = fmaxf(vv.x + bb.x, 0.f);
            o.y = fmaxf(vv.y + bb.y, 0.f);
            o.z = fmaxf(vv.z + bb.z, 0.f);
            o.w = fmaxf(vv.w + bb.w, 0.f);
            ((float4*)&Y2[(size_t)row * DD + c0])[c4] = o;
        }
    }
}

// ---------------- CSR aggregation + combine + BN stats (+ pooling on last layer) ----------------
__global__ void k_agg(const float* __restrict__ bg, int zpool, int do_pool,
                      const int* __restrict__ gid, const int* __restrict__ mid) {
    __shared__ float ssum[8][DD];
    __shared__ float ssq[8][DD];
    int tid = threadIdx.x;
    int w = tid >> 5;
    int lane = tid & 31;

    if (zpool) {
        int gstep = gridDim.x * blockDim.x;
        int gidx = blockIdx.x * blockDim.x + tid;
        for (int i = gidx; i < GG * DD; i += gstep) g_gsum[i] = 0.f;
        for (int i = gidx; i < (MM + 1) * DD; i += gstep) g_msum[i] = 0.f;
        for (int i = gidx; i < GG; i += gstep) g_gcnt[i] = 0.f;
        for (int i = gidx; i < MM + 1; i += gstep) g_mcnt[i] = 0.f;
    }

    int node = blockIdx.x * 8 + w;
    float4 y = make_float4(0.f, 0.f, 0.f, 0.f);
    if (node < NN) {
        int e0 = g_rowstart[node], e1 = g_rowstart[node + 1];
        float4 acc[8];
#pragma unroll
        for (int i = 0; i < 8; i++) acc[i] = make_float4(0.f, 0.f, 0.f, 0.f);
        int e = e0;
        for (; e + 8 <= e1; e += 8) {
            float4 v[8];
#pragma unroll
            for (int i = 0; i < 8; i++) {
                int s = g_csr_src[e + i];
                v[i] = ((const float4*)(g_bufB + (size_t)s * DD))[lane];
            }
#pragma unroll
            for (int i = 0; i < 8; i++) {
                acc[i].x += v[i].x; acc[i].y += v[i].y;
                acc[i].z += v[i].z; acc[i].w += v[i].w;
            }
        }
        if (e + 4 <= e1) {
            float4 v[4];
#pragma unroll
            for (int i = 0; i < 4; i++) {
                int s = g_csr_src[e + i];
                v[i] = ((const float4*)(g_bufB + (size_t)s * DD))[lane];
            }
#pragma unroll
            for (int i = 0; i < 4; i++) {
                acc[i].x += v[i].x; acc[i].y += v[i].y;
                acc[i].z += v[i].z; acc[i].w += v[i].w;
            }
            e += 4;
        }
        for (; e < e1; e++) {
            int s = g_csr_src[e];
            float4 v0 = ((const float4*)(g_bufB + (size_t)s * DD))[lane];
            acc[0].x += v0.x; acc[0].y += v0.y; acc[0].z += v0.z; acc[0].w += v0.w;
        }
#pragma unroll
        for (int i = 4; i < 8; i++) {
            acc[i - 4].x += acc[i].x; acc[i - 4].y += acc[i].y;
            acc[i - 4].z += acc[i].z; acc[i - 4].w += acc[i].w;
        }
        acc[0].x += acc[2].x + acc[1].x + acc[3].x;
        acc[0].y += acc[2].y + acc[1].y + acc[3].y;
        acc[0].z += acc[2].z + acc[1].z + acc[3].z;
        acc[0].w += acc[2].w + acc[1].w + acc[3].w;

        float nd = g_norm_dst[node];
        float4 b4 = ((const float4*)bg)[lane];
        float4 r = ((const float4*)(g_bufR + (size_t)node * DD))[lane];
        y.x = fmaxf(fmaf(acc[0].x, nd, b4.x), 0.f) + r.x;
        y.y = fmaxf(fmaf(acc[0].y, nd, b4.y), 0.f) + r.y;
        y.z = fmaxf(fmaf(acc[0].z, nd, b4.z), 0.f) + r.z;
        y.w = fmaxf(fmaf(acc[0].w, nd, b4.w), 0.f) + r.w;

        if (do_pool) {
            int gi = gid[node], mi = mid[node];
            atomicAdd(((float4*)(g_gsum + (size_t)gi * DD)) + lane, y);
            atomicAdd(((float4*)(g_msum + (size_t)mi * DD)) + lane, y);
            if (lane == 0) {
                atomicAdd(&g_gcnt[gi], 1.0f);
                atomicAdd(&g_mcnt[mi], 1.0f);
            }
        } else {
            ((float4*)(g_bufA + (size_t)node * DD))[lane] = y;
        }
    }
    ((float4*)&ssum[w][0])[lane] = y;
    float4 y2 = make_float4(y.x * y.x, y.y * y.y, y.z * y.z, y.w * y.w);
    ((float4*)&ssq[w][0])[lane] = y2;
    __syncthreads();
    if (tid < DD) {
        float s = 0.f;
#pragma unroll
        for (int i = 0; i < 8; i++) s += ssum[i][tid];
        atomicAdd(&g_stats[tid], s);
    } else {
        int j = tid - DD;
        float s = 0.f;
#pragma unroll
        for (int i = 0; i < 8; i++) s += ssq[i][j];
        atomicAdd(&g_stats[DD + j], s);
    }
}

// ---------------- BN prep ----------------
__global__ void k_bnprep(const float* __restrict__ gamma, const float* __restrict__ beta) {
    int j = threadIdx.x;
    float invN = 1.0f / (float)NN;
    float mu = g_stats[j] * invN;
    float var = fmaxf(g_stats[DD + j] * invN - mu * mu, 0.f);
    float s = gamma[j] * rsqrtf(var + BN_EPS);
    g_cs[j] = s;
    g_cb[j] = beta[j] - mu * s;
    g_stats[j] = 0.f;
    g_stats[DD + j] = 0.f;
}

// ---------------- finalize: mean pools + layer-2 BN affine ----------------
__global__ void k_finalize(float* __restrict__ out_gf) {
    int idx = blockIdx.x * blockDim.x + threadIdx.x;
    if (idx >= (GG + MM) * DD) return;
    int row = idx / DD, j = idx % DD;
    float cs = g_cs[j], cb = g_cb[j];
    float v;
    if (row < GG) {
        v = cs * g_gsum[row * DD + j] / fmaxf(g_gcnt[row], 1.0f) + cb;
        out_gf[row * DD + j] = v;
    } else {
        int mrow = row - GG + 1;
        v = cs * g_msum[mrow * DD + j] / fmaxf(g_mcnt[mrow], 1.0f) + cb;
    }
    g_headin[idx] = v;
}

// ---------------- fp32 tiled GEMM with f32x2 (head MLP) ----------------
__global__ void k_gemm(const float* __restrict__ X, const float* __restrict__ W,
                       const float* __restrict__ bias,
                       float* __restrict__ Y, int nrows, int K, int ncols, int do_relu) {
    extern __shared__ float sm[];
    float* Ws = sm;
    float* Xs = sm + 128 * 128;
    const int tid = threadIdx.x;
    const int tx = tid & 31;
    const int ty = tid >> 5;
    const int r0 = blockIdx.x * 64;
    const int c0 = blockIdx.y * 128;

    unsigned long long acc[8][2];
#pragma unroll
    for (int m = 0; m < 8; m++) acc[m][0] = acc[m][1] = 0ull;

    for (int kb = 0; kb < K; kb += 128) {
#pragma unroll
        for (int i = 0; i < 16; i++) {
            int f = tid + 256 * i;
            int r = f >> 5, c4 = f & 31;
            ((float4*)Ws)[f] = *(const float4*)&W[(size_t)(kb + r) * ncols + c0 + c4 * 4];
        }
#pragma unroll
        for (int i = 0; i < 8; i++) {
            int f = tid + 256 * i;
            int m = f >> 5, k4 = f & 31;
            int row = r0 + m;
            float4 v = make_float4(0.f, 0.f, 0.f, 0.f);
            if (row < nrows) v = *(const float4*)&X[(size_t)row * K + kb + k4 * 4];
            ((float4*)Xs)[f] = v;
        }
        __syncthreads();

#pragma unroll 2
        for (int k = 0; k < 128; k += 4) {
            float4 xv[8];
#pragma unroll
            for (int m = 0; m < 8; m++)
                xv[m] = *(const float4*)&Xs[(ty * 8 + m) * 128 + k];
#pragma unroll
            for (int kk = 0; kk < 4; kk++) {
                ulonglong2 w = *(const ulonglong2*)&Ws[(k + kk) * 128 + tx * 4];
#pragma unroll
                for (int m = 0; m < 8; m++) {
                    float x = (kk == 0) ? xv[m].x : (kk == 1) ? xv[m].y
                            : (kk == 2) ? xv[m].z : xv[m].w;
                    unsigned long long xp = pack_dup(x);
                    ffma2(acc[m][0], xp, w.x);
                    ffma2(acc[m][1], xp, w.y);
                }
            }
        }
        __syncthreads();
    }

    float4 b4 = make_float4(0.f, 0.f, 0.f, 0.f);
    if (bias) b4 = *(const float4*)&bias[c0 + tx * 4];
#pragma unroll
    for (int m = 0; m < 8; m++) {
        int row = r0 + ty * 8 + m;
        if (row < nrows) {
            float2 p0 = unpack2(acc[m][0]);
            float2 p1 = unpack2(acc[m][1]);
            float4 o;
            o.x = p0.x + b4.x; o.y = p0.y + b4.y;
            o.z = p1.x + b4.z; o.w = p1.y + b4.w;
            if (do_relu) {
                o.x = fmaxf(o.x, 0.f); o.y = fmaxf(o.y, 0.f);
                o.z = fmaxf(o.z, 0.f); o.w = fmaxf(o.w, 0.f);
            }
            *(float4*)&Y[(size_t)row * ncols + c0 + tx * 4] = o;
        }
    }
}

// ---------------- launch ----------------
extern "C" void kernel_launch(void* const* d_in, const int* in_sizes, int n_in,
                              void* d_out, int out_size) {
    const float* node_feats = (const float*)d_in[0];
    const int*   src        = (const int*)d_in[1];
    const int*   dst        = (const int*)d_in[2];
    const int*   gid        = (const int*)d_in[3];
    const int*   mid        = (const int*)d_in[4];
    const float* Wg         = (const float*)d_in[5];
    const float* bg         = (const float*)d_in[6];
    const float* Wr         = (const float*)d_in[7];
    const float* br         = (const float*)d_in[8];
    const float* gamma      = (const float*)d_in[9];
    const float* beta       = (const float*)d_in[10];
    const float* W_feat     = (const float*)d_in[11];
    const float* b_feat     = (const float*)d_in[12];
    const float* W1         = (const float*)d_in[13];
    const float* b1         = (const float*)d_in[14];
    const float* W2         = (const float*)d_in[15];
    const float* b2         = (const float*)d_in[16];
    float* out = (float*)d_out;

    void *pA, *pns, *phin, *ph1, *ph2, *pB, *pR, *pwp1, *pwp2, *pbc1, *pbc2, *pz;
    cudaGetSymbolAddress(&pA, g_bufA);
    cudaGetSymbolAddress(&pB, g_bufB);
    cudaGetSymbolAddress(&pR, g_bufR);
    cudaGetSymbolAddress(&pns, g_norm_src);
    cudaGetSymbolAddress(&phin, g_headin);
    cudaGetSymbolAddress(&ph1, g_head1);
    cudaGetSymbolAddress(&ph2, g_head2);
    cudaGetSymbolAddress(&pwp1, g_wp1);
    cudaGetSymbolAddress(&pwp2, g_wp2);
    cudaGetSymbolAddress(&pbc1, g_bc1);
    cudaGetSymbolAddress(&pbc2, g_bc2);
    cudaGetSymbolAddress(&pz, g_zero);

    const int SMEM_G = (128 * 128 + 64 * 128) * 4;   // 96 KB (head gemm)
    const int SMEM_D = 6 * 128 * LDP * 2;            // 110592 B (dual gemm, bf16 split)
    cudaFuncSetAttribute(k_gemm, cudaFuncAttributeMaxDynamicSharedMemorySize, SMEM_G);
    cudaFuncSetAttribute(k_dualgemm, cudaFuncAttributeMaxDynamicSharedMemorySize, SMEM_D);

    const int gemm_rows = (NN + 127) / 128;   // 391
    const int agg_blocks = (NN + 7) / 8;      // 6250

    // ---- setup ----
    k_zero<<<(NN + 255) / 256, 256>>>();
    k_hist<<<(EE + 255) / 256, 256>>>(src, dst);
    k_norms<<<(NN + 255) / 256, 256>>>();

    // ---- layer-0 dual GEMM (4th launch, ncu-captured): raw weights, b1c=0, b2c=br ----
    k_dualgemm<<<dim3(gemm_rows, 2), 256, SMEM_D>>>(
        node_feats, Wg, Wr, (const float*)pz, br, (const float*)pns,
        (float*)pB, (float*)pR, NN);

    // ---- CSR build (stream-ordered before k_agg) ----
    k_scan1<<<SCAN_B, 256>>>();
    k_scan2<<<1, 256>>>();
    k_scan3<<<SCAN_B, 256>>>();
    k_place<<<(EE + 255) / 256, 256>>>(src, dst);

    for (int l = 0; l < LL; l++) {
        if (l > 0) {
            k_wprep<<<DD, DD>>>(Wg + (size_t)l * DD * DD, Wr + (size_t)l * DD * DD);
            k_wbias<<<1, 2 * DD>>>(Wg + (size_t)l * DD * DD, Wr + (size_t)l * DD * DD,
                                   br + (size_t)l * DD);
            k_dualgemm<<<dim3(gemm_rows, 2), 256, SMEM_D>>>(
                (const float*)pA, (const float*)pwp1, (const float*)pwp2,
                (const float*)pbc1, (const float*)pbc2, (const float*)pns,
                (float*)pB, (float*)pR, NN);
        }

        k_agg<<<agg_blocks, 256>>>(bg + (size_t)l * DD,
                                   (l == 0) ? 1 : 0,
                                   (l == LL - 1) ? 1 : 0,
                                   gid, mid);

        k_bnprep<<<1, DD>>>(gamma + (size_t)l * DD, beta + (size_t)l * DD);
    }

    // ---- finalize: mean pools + layer-2 BN affine ----
    k_finalize<<<((GG + MM) * DD + 255) / 256, 256>>>(out);

    // ---- head MLP on [graph_feats ; h_sub] = 2560 rows ----
    const int HR = GG + MM;
    const int hblocks = (HR + 63) / 64;
    k_gemm<<<dim3(hblocks, FFN / 128), 256, SMEM_G>>>(
        (const float*)phin, W_feat, b_feat, (float*)ph1, HR, DD, FFN, 0);
    k_gemm<<<dim3(hblocks, FFN / 128), 256, SMEM_G>>>(
        (const float*)ph1, W1, b1, (float*)ph2, HR, FFN, FFN, 1);
    k_gemm<<<dim3(hblocks, 1), 256, SMEM_G>>>(
        (const float*)ph2, W2, b2, out + (size_t)GG * DD, HR, FFN, DD, 0);
}

// round 12
// speedup vs baseline: 1.1899x; 1.0107x over previous
#include <cuda_runtime.h>
#include <cuda_bf16.h>
#include <mma.h>
#include <cstddef>

using namespace nvcuda;

#define NN 50000
#define EE 600000
#define GG 512
#define MM 2048
#define DD 128
#define FFN 256
#define LL 3
#define BN_EPS 1e-5f
#define SCAN_B 196   // ceil(NN/256)
#define LDP 72       // padded bf16 row length (144B) -> conflict-free ldmatrix

// ---------------- scratch (device globals) ----------------
__device__ float g_bufA[NN * DD];   // layer output h (raw, pre-BN)
__device__ float g_bufB[NN * DD];   // hw branch
__device__ float g_bufR[NN * DD];   // residual branch
__device__ int   g_degin[NN];
__device__ int   g_degout[NN];
__device__ int   g_cursor[NN];
__device__ int   g_rowstart[NN + 1];
__device__ int   g_csr_src[EE];
__device__ int   g_bsum[SCAN_B];
__device__ int   g_boff[SCAN_B];
__device__ float g_norm_src[NN];
__device__ float g_norm_dst[NN];
__device__ float g_stats[2 * DD];
__device__ float g_cs[DD];
__device__ float g_cb[DD];
__device__ float g_zero[DD];
__device__ float g_wp1[DD * DD];    // cs-scaled Wg[l]
__device__ float g_wp2[DD * DD];    // cs-scaled Wr[l]
__device__ float g_bc1[DD];         // cb @ Wg[l]
__device__ float g_bc2[DD];         // cb @ Wr[l] + br[l]
__device__ float g_gsum[GG * DD];
__device__ float g_gcnt[GG];
__device__ float g_msum[(MM + 1) * DD];
__device__ float g_mcnt[MM + 1];
__device__ float g_headin[(GG + MM) * DD];
__device__ float g_head1[(GG + MM) * FFN];
__device__ float g_head2[(GG + MM) * FFN];

// ---------------- f32x2 helpers (head GEMM) ----------------
__device__ __forceinline__ unsigned long long pack_dup(float x) {
    unsigned long long p;
    unsigned int xb = __float_as_uint(x);
    asm("mov.b64 %0, {%1, %1};" : "=l"(p) : "r"(xb));
    return p;
}
__device__ __forceinline__ void ffma2(unsigned long long& acc, unsigned long long a,
                                      unsigned long long b) {
    asm("fma.rn.f32x2 %0, %1, %2, %0;" : "+l"(acc) : "l"(a), "l"(b));
}
__device__ __forceinline__ float2 unpack2(unsigned long long a) {
    float lo, hi;
    asm("mov.b64 {%0, %1}, %2;" : "=f"(lo), "=f"(hi) : "l"(a));
    return make_float2(lo, hi);
}

// ---------------- bf16 hi/lo split store (4 values) ----------------
__device__ __forceinline__ void split_store(__nv_bfloat16* ph, __nv_bfloat16* pl, float4 v) {
    __nv_bfloat162 h01 = __floats2bfloat162_rn(v.x, v.y);
    __nv_bfloat162 h23 = __floats2bfloat162_rn(v.z, v.w);
    float2 f01 = __bfloat1622float2(h01);
    float2 f23 = __bfloat1622float2(h23);
    __nv_bfloat162 l01 = __floats2bfloat162_rn(v.x - f01.x, v.y - f01.y);
    __nv_bfloat162 l23 = __floats2bfloat162_rn(v.z - f23.x, v.w - f23.y);
    uint2 hv, lv;
    hv.x = *(unsigned*)&h01; hv.y = *(unsigned*)&h23;
    lv.x = *(unsigned*)&l01; lv.y = *(unsigned*)&l23;
    *(uint2*)ph = hv;
    *(uint2*)pl = lv;
}

// ---------------- setup ----------------
__global__ void k_zero() {
    int i = blockIdx.x * blockDim.x + threadIdx.x;
    if (i < NN) { g_degin[i] = 0; g_degout[i] = 0; }
}

__global__ void k_hist(const int* __restrict__ src, const int* __restrict__ dst) {
    int e = blockIdx.x * blockDim.x + threadIdx.x;
    if (e < EE) {
        atomicAdd(&g_degout[src[e]], 1);
        atomicAdd(&g_degin[dst[e]], 1);
    }
}

__global__ void k_norms() {
    int i = blockIdx.x * blockDim.x + threadIdx.x;
    if (i < NN) {
        g_norm_src[i] = rsqrtf(fmaxf((float)g_degout[i], 1.0f));
        g_norm_dst[i] = rsqrtf(fmaxf((float)g_degin[i], 1.0f));
    }
    if (i < 2 * DD) g_stats[i] = 0.f;
    if (i < DD) g_zero[i] = 0.f;
}

// ---------------- multi-block scan of g_degin -> g_rowstart ----------------
__global__ void k_scan1() {
    __shared__ int sh[256];
    int tid = threadIdx.x;
    int i = blockIdx.x * 256 + tid;
    int v = (i < NN) ? g_degin[i] : 0;
    if (i < NN) g_cursor[i] = 0;
    sh[tid] = v;
    __syncthreads();
    for (int off = 128; off > 0; off >>= 1) {
        if (tid < off) sh[tid] += sh[tid + off];
        __syncthreads();
    }
    if (tid == 0) g_bsum[blockIdx.x] = sh[0];
}

__global__ void k_scan2() {
    __shared__ int sh[256];
    int tid = threadIdx.x;
    int v = (tid < SCAN_B) ? g_bsum[tid] : 0;
    sh[tid] = v;
    __syncthreads();
    for (int off = 1; off < 256; off <<= 1) {
        int t = (tid >= off) ? sh[tid - off] : 0;
        __syncthreads();
        sh[tid] += t;
        __syncthreads();
    }
    if (tid < SCAN_B) g_boff[tid] = sh[tid] - v;
}

__global__ void k_scan3() {
    __shared__ int sh[256];
    int tid = threadIdx.x;
    int i = blockIdx.x * 256 + tid;
    int v = (i < NN) ? g_degin[i] : 0;
    sh[tid] = v;
    __syncthreads();
    for (int off = 1; off < 256; off <<= 1) {
        int t = (tid >= off) ? sh[tid - off] : 0;
        __syncthreads();
        sh[tid] += t;
        __syncthreads();
    }
    if (i < NN) g_rowstart[i] = sh[tid] - v + g_boff[blockIdx.x];
    if (blockIdx.x == 0 && tid == 0) g_rowstart[NN] = EE;
}

__global__ void k_place(const int* __restrict__ src, const int* __restrict__ dst) {
    int e = blockIdx.x * blockDim.x + threadIdx.x;
    if (e < EE) {
        int d = dst[e];
        int slot = atomicAdd(&g_cursor[d], 1);
        g_csr_src[g_rowstart[d] + slot] = src[e];
    }
}

// ---------------- BN-affine weight prep (layers 1,2) ----------------
__global__ void k_wprep(const float* __restrict__ W1, const float* __restrict__ W2) {
    int k = blockIdx.x, c = threadIdx.x;
    float s = g_cs[k];
    g_wp1[k * DD + c] = s * W1[k * DD + c];
    g_wp2[k * DD + c] = s * W2[k * DD + c];
}

__global__ void k_wbias(const float* __restrict__ W1, const float* __restrict__ W2,
                        const float* __restrict__ br) {
    int tid = threadIdx.x;   // 256
    int c = tid & (DD - 1);
    const float* W = (tid < DD) ? W1 : W2;
    float s = 0.f;
#pragma unroll 16
    for (int k = 0; k < DD; k++) s += g_cb[k] * W[k * DD + c];
    if (tid < DD) g_bc1[c] = s;
    else          g_bc2[c] = s + br[c];
}

// ---------------- dual GEMM: split-bf16 tensor cores (3-term, ~fp32 accuracy) ----------------
__global__ void __launch_bounds__(256)
k_dualgemm(const float* __restrict__ X,
           const float* __restrict__ W1f,
           const float* __restrict__ W2f,
           const float* __restrict__ b1c,
           const float* __restrict__ b2c,
           const float* __restrict__ rs,
           float* __restrict__ Y1, float* __restrict__ Y2,
           int nrows) {
    extern __shared__ __nv_bfloat16 smb[];
    __nv_bfloat16* W1h = smb;                    // 128*LDP each (18 KB)
    __nv_bfloat16* W1l = W1h + 128 * LDP;
    __nv_bfloat16* W2h = W1l + 128 * LDP;
    __nv_bfloat16* W2l = W2h + 128 * LDP;
    __nv_bfloat16* Xh  = W2l + 128 * LDP;
    __nv_bfloat16* Xl  = Xh + 128 * LDP;
    float* stage = (float*)Xh;

    const int tid = threadIdx.x;
    const int w = tid >> 5;
    const int wr = (w & 3) * 32;
    const int wc = (w >> 2) * 32;
    const int r0 = blockIdx.x * 128;
    const int c0 = blockIdx.y * 64;

    // prefetch X chunk 0 (k 0..63)
    float4 xreg[8];
#pragma unroll
    for (int i = 0; i < 8; i++) {
        int f = tid + 256 * i;
        int rl = f >> 4, j4 = f & 15;
        int row = r0 + rl;
        xreg[i] = make_float4(0.f, 0.f, 0.f, 0.f);
        if (row < nrows) xreg[i] = *(const float4*)&X[(size_t)row * DD + j4 * 4];
    }

    // convert W tiles once
#pragma unroll
    for (int i = 0; i < 8; i++) {
        int f = tid + 256 * i;
        int k = f >> 4, c4 = f & 15;
        float4 v1 = ((const float4*)&W1f[(size_t)k * DD + c0])[c4];
        float4 v2 = ((const float4*)&W2f[(size_t)k * DD + c0])[c4];
        split_store(W1h + k * LDP + c4 * 4, W1l + k * LDP + c4 * 4, v1);
        split_store(W2h + k * LDP + c4 * 4, W2l + k * LDP + c4 * 4, v2);
    }

    wmma::fragment<wmma::accumulator, 16, 16, 16, float> acc1[2][2], acc2[2][2];
#pragma unroll
    for (int i = 0; i < 2; i++)
#pragma unroll
        for (int j = 0; j < 2; j++) {
            wmma::fill_fragment(acc1[i][j], 0.f);
            wmma::fill_fragment(acc2[i][j], 0.f);
        }

#pragma unroll 1
    for (int kc = 0; kc < 2; kc++) {
        __syncthreads();
#pragma unroll
        for (int i = 0; i < 8; i++) {
            int f = tid + 256 * i;
            int rl = f >> 4, j4 = f & 15;
            split_store(Xh + rl * LDP + j4 * 4, Xl + rl * LDP + j4 * 4, xreg[i]);
        }
        if (kc == 0) {
#pragma unroll
            for (int i = 0; i < 8; i++) {
                int f = tid + 256 * i;
                int rl = f >> 4, j4 = f & 15;
                int row = r0 + rl;
                xreg[i] = make_float4(0.f, 0.f, 0.f, 0.f);
                if (row < nrows) xreg[i] = *(const float4*)&X[(size_t)row * DD + 64 + j4 * 4];
            }
        }
        __syncthreads();

#pragma unroll
        for (int ks = 0; ks < 64; ks += 16) {
            wmma::fragment<wmma::matrix_a, 16, 16, 16, __nv_bfloat16, wmma::row_major> ah[2], al[2];
#pragma unroll
            for (int i = 0; i < 2; i++) {
                wmma::load_matrix_sync(ah[i], Xh + (wr + 16 * i) * LDP + ks, LDP);
                wmma::load_matrix_sync(al[i], Xl + (wr + 16 * i) * LDP + ks, LDP);
            }
            int kg = kc * 64 + ks;
#pragma unroll
            for (int j = 0; j < 2; j++) {
                wmma::fragment<wmma::matrix_b, 16, 16, 16, __nv_bfloat16, wmma::row_major> bh, bl;
                wmma::load_matrix_sync(bh, W1h + kg * LDP + wc + 16 * j, LDP);
                wmma::load_matrix_sync(bl, W1l + kg * LDP + wc + 16 * j, LDP);
#pragma unroll
                for (int i = 0; i < 2; i++) {
                    wmma::mma_sync(acc1[i][j], ah[i], bh, acc1[i][j]);
                    wmma::mma_sync(acc1[i][j], ah[i], bl, acc1[i][j]);
                    wmma::mma_sync(acc1[i][j], al[i], bh, acc1[i][j]);
                }
                wmma::load_matrix_sync(bh, W2h + kg * LDP + wc + 16 * j, LDP);
                wmma::load_matrix_sync(bl, W2l + kg * LDP + wc + 16 * j, LDP);
#pragma unroll
                for (int i = 0; i < 2; i++) {
                    wmma::mma_sync(acc2[i][j], ah[i], bh, acc2[i][j]);
                    wmma::mma_sync(acc2[i][j], ah[i], bl, acc2[i][j]);
                    wmma::mma_sync(acc2[i][j], al[i], bh, acc2[i][j]);
                }
            }
        }
    }

    // ---- epilogue via fp32 staging ----
    __syncthreads();
#pragma unroll
    for (int i = 0; i < 2; i++)
#pragma unroll
        for (int j = 0; j < 2; j++)
            wmma::store_matrix_sync(stage + (wr + 16 * i) * LDP + wc + 16 * j,
                                    acc1[i][j], LDP, wmma::mem_row_major);
    __syncthreads();
#pragma unroll
    for (int i = 0; i < 8; i++) {
        int f = tid + 256 * i;
        int rl = f >> 4, c4 = f & 15;
        int row = r0 + rl;
        if (row < nrows) {
            float s = rs[row];
            float4 vv = *(const float4*)&stage[rl * LDP + c4 * 4];
            float4 bb = ((const float4*)&b1c[c0])[c4];
            float4 o;
            o.x = (vv.x + bb.x) * s; o.y = (vv.y + bb.y) * s;
            o.z = (vv.z + bb.z) * s; o.w = (vv.w + bb.w) * s;
            ((float4*)&Y1[(size_t)row * DD + c0])[c4] = o;
        }
    }
    __syncthreads();
#pragma unroll
    for (int i = 0; i < 2; i++)
#pragma unroll
        for (int j = 0; j < 2; j++)
            wmma::store_matrix_sync(stage + (wr + 16 * i) * LDP + wc + 16 * j,
                                    acc2[i][j], LDP, wmma::mem_row_major);
    __syncthreads();
#pragma unroll
    for (int i = 0; i < 8; i++) {
        int f = tid + 256 * i;
        int rl = f >> 4, c4 = f & 15;
        int row = r0 + rl;
        if (row < nrows) {
            float4 vv = *(const float4*)&stage[rl * LDP + c4 * 4];
            float4 bb = ((const float4*)&b2c[c0])[c4];
            float4 o;
            o.x = fmaxf(vv.x + bb.x, 0.f);
            o.y = fmaxf(vv.y + bb.y, 0.f);
            o.z = fmaxf(vv.z + bb.z, 0.f);
            o.w = fmaxf(vv.w + bb.w, 0.f);
            ((float4*)&Y2[(size_t)row * DD + c0])[c4] = o;
        }
    }
}

// ---------------- CSR aggregation + combine + BN stats (+ pooling on last layer) ----------------
// 16 edges in flight per warp (batched predicated gathers -> MLP ~16).
__global__ void k_agg(const float* __restrict__ bg, int zpool, int do_pool,
                      const int* __restrict__ gid, const int* __restrict__ mid) {
    __shared__ float ssum[8][DD];
    __shared__ float ssq[8][DD];
    int tid = threadIdx.x;
    int w = tid >> 5;
    int lane = tid & 31;

    if (zpool) {
        int gstep = gridDim.x * blockDim.x;
        int gidx = blockIdx.x * blockDim.x + tid;
        for (int i = gidx; i < GG * DD; i += gstep) g_gsum[i] = 0.f;
        for (int i = gidx; i < (MM + 1) * DD; i += gstep) g_msum[i] = 0.f;
        for (int i = gidx; i < GG; i += gstep) g_gcnt[i] = 0.f;
        for (int i = gidx; i < MM + 1; i += gstep) g_mcnt[i] = 0.f;
    }

    int node = blockIdx.x * 8 + w;
    float4 y = make_float4(0.f, 0.f, 0.f, 0.f);
    if (node < NN) {
        int e0 = g_rowstart[node], e1 = g_rowstart[node + 1];
        float4 acc[4];
#pragma unroll
        for (int i = 0; i < 4; i++) acc[i] = make_float4(0.f, 0.f, 0.f, 0.f);

        for (int base = e0; base < e1; base += 16) {
            int n = e1 - base;            // >=1
            float4 v[16];
#pragma unroll
            for (int i = 0; i < 16; i++) {
                v[i] = make_float4(0.f, 0.f, 0.f, 0.f);
                if (i < n) {
                    int s = g_csr_src[base + i];
                    v[i] = ((const float4*)(g_bufB + (size_t)s * DD))[lane];
                }
            }
#pragma unroll
            for (int i = 0; i < 16; i++) {
                acc[i & 3].x += v[i].x; acc[i & 3].y += v[i].y;
                acc[i & 3].z += v[i].z; acc[i & 3].w += v[i].w;
            }
        }
        acc[0].x += acc[1].x + acc[2].x + acc[3].x;
        acc[0].y += acc[1].y + acc[2].y + acc[3].y;
        acc[0].z += acc[1].z + acc[2].z + acc[3].z;
        acc[0].w += acc[1].w + acc[2].w + acc[3].w;

        float nd = g_norm_dst[node];
        float4 b4 = ((const float4*)bg)[lane];
        float4 r = ((const float4*)(g_bufR + (size_t)node * DD))[lane];
        y.x = fmaxf(fmaf(acc[0].x, nd, b4.x), 0.f) + r.x;
        y.y = fmaxf(fmaf(acc[0].y, nd, b4.y), 0.f) + r.y;
        y.z = fmaxf(fmaf(acc[0].z, nd, b4.z), 0.f) + r.z;
        y.w = fmaxf(fmaf(acc[0].w, nd, b4.w), 0.f) + r.w;

        if (do_pool) {
            int gi = gid[node], mi = mid[node];
            atomicAdd(((float4*)(g_gsum + (size_t)gi * DD)) + lane, y);
            atomicAdd(((float4*)(g_msum + (size_t)mi * DD)) + lane, y);
            if (lane == 0) {
                atomicAdd(&g_gcnt[gi], 1.0f);
                atomicAdd(&g_mcnt[mi], 1.0f);
            }
        } else {
            ((float4*)(g_bufA + (size_t)node * DD))[lane] = y;
        }
    }
    ((float4*)&ssum[w][0])[lane] = y;
    float4 y2 = make_float4(y.x * y.x, y.y * y.y, y.z * y.z, y.w * y.w);
    ((float4*)&ssq[w][0])[lane] = y2;
    __syncthreads();
    if (tid < DD) {
        float s = 0.f;
#pragma unroll
        for (int i = 0; i < 8; i++) s += ssum[i][tid];
        atomicAdd(&g_stats[tid], s);
    } else {
        int j = tid - DD;
        float s = 0.f;
#pragma unroll
        for (int i = 0; i < 8; i++) s += ssq[i][j];
        atomicAdd(&g_stats[DD + j], s);
    }
}

// ---------------- BN prep ----------------
__global__ void k_bnprep(const float* __restrict__ gamma, const float* __restrict__ beta) {
    int j = threadIdx.x;
    float invN = 1.0f / (float)NN;
    float mu = g_stats[j] * invN;
    float var = fmaxf(g_stats[DD + j] * invN - mu * mu, 0.f);
    float s = gamma[j] * rsqrtf(var + BN_EPS);
    g_cs[j] = s;
    g_cb[j] = beta[j] - mu * s;
    g_stats[j] = 0.f;
    g_stats[DD + j] = 0.f;
}

// ---------------- finalize: mean pools + layer-2 BN affine ----------------
__global__ void k_finalize(float* __restrict__ out_gf) {
    int idx = blockIdx.x * blockDim.x + threadIdx.x;
    if (idx >= (GG + MM) * DD) return;
    int row = idx / DD, j = idx % DD;
    float cs = g_cs[j], cb = g_cb[j];
    float v;
    if (row < GG) {
        v = cs * g_gsum[row * DD + j] / fmaxf(g_gcnt[row], 1.0f) + cb;
        out_gf[row * DD + j] = v;
    } else {
        int mrow = row - GG + 1;
        v = cs * g_msum[mrow * DD + j] / fmaxf(g_mcnt[mrow], 1.0f) + cb;
    }
    g_headin[idx] = v;
}

// ---------------- fp32 tiled GEMM with f32x2 (head MLP) ----------------
__global__ void k_gemm(const float* __restrict__ X, const float* __restrict__ W,
                       const float* __restrict__ bias,
                       float* __restrict__ Y, int nrows, int K, int ncols, int do_relu) {
    extern __shared__ float sm[];
    float* Ws = sm;
    float* Xs = sm + 128 * 128;
    const int tid = threadIdx.x;
    const int tx = tid & 31;
    const int ty = tid >> 5;
    const int r0 = blockIdx.x * 64;
    const int c0 = blockIdx.y * 128;

    unsigned long long acc[8][2];
#pragma unroll
    for (int m = 0; m < 8; m++) acc[m][0] = acc[m][1] = 0ull;

    for (int kb = 0; kb < K; kb += 128) {
#pragma unroll
        for (int i = 0; i < 16; i++) {
            int f = tid + 256 * i;
            int r = f >> 5, c4 = f & 31;
            ((float4*)Ws)[f] = *(const float4*)&W[(size_t)(kb + r) * ncols + c0 + c4 * 4];
        }
#pragma unroll
        for (int i = 0; i < 8; i++) {
            int f = tid + 256 * i;
            int m = f >> 5, k4 = f & 31;
            int row = r0 + m;
            float4 v = make_float4(0.f, 0.f, 0.f, 0.f);
            if (row < nrows) v = *(const float4*)&X[(size_t)row * K + kb + k4 * 4];
            ((float4*)Xs)[f] = v;
        }
        __syncthreads();

#pragma unroll 2
        for (int k = 0; k < 128; k += 4) {
            float4 xv[8];
#pragma unroll
            for (int m = 0; m < 8; m++)
                xv[m] = *(const float4*)&Xs[(ty * 8 + m) * 128 + k];
#pragma unroll
            for (int kk = 0; kk < 4; kk++) {
                ulonglong2 w = *(const ulonglong2*)&Ws[(k + kk) * 128 + tx * 4];
#pragma unroll
                for (int m = 0; m < 8; m++) {
                    float x = (kk == 0) ? xv[m].x : (kk == 1) ? xv[m].y
                            : (kk == 2) ? xv[m].z : xv[m].w;
                    unsigned long long xp = pack_dup(x);
                    ffma2(acc[m][0], xp, w.x);
                    ffma2(acc[m][1], xp, w.y);
                }
            }
        }
        __syncthreads();
    }

    float4 b4 = make_float4(0.f, 0.f, 0.f, 0.f);
    if (bias) b4 = *(const float4*)&bias[c0 + tx * 4];
#pragma unroll
    for (int m = 0; m < 8; m++) {
        int row = r0 + ty * 8 + m;
        if (row < nrows) {
            float2 p0 = unpack2(acc[m][0]);
            float2 p1 = unpack2(acc[m][1]);
            float4 o;
            o.x = p0.x + b4.x; o.y = p0.y + b4.y;
            o.z = p1.x + b4.z; o.w = p1.y + b4.w;
            if (do_relu) {
                o.x = fmaxf(o.x, 0.f); o.y = fmaxf(o.y, 0.f);
                o.z = fmaxf(o.z, 0.f); o.w = fmaxf(o.w, 0.f);
            }
            *(float4*)&Y[(size_t)row * ncols + c0 + tx * 4] = o;
        }
    }
}

// ---------------- launch ----------------
extern "C" void kernel_launch(void* const* d_in, const int* in_sizes, int n_in,
                              void* d_out, int out_size) {
    const float* node_feats = (const float*)d_in[0];
    const int*   src        = (const int*)d_in[1];
    const int*   dst        = (const int*)d_in[2];
    const int*   gid        = (const int*)d_in[3];
    const int*   mid        = (const int*)d_in[4];
    const float* Wg         = (const float*)d_in[5];
    const float* bg         = (const float*)d_in[6];
    const float* Wr         = (const float*)d_in[7];
    const float* br         = (const float*)d_in[8];
    const float* gamma      = (const float*)d_in[9];
    const float* beta       = (const float*)d_in[10];
    const float* W_feat     = (const float*)d_in[11];
    const float* b_feat     = (const float*)d_in[12];
    const float* W1         = (const float*)d_in[13];
    const float* b1         = (const float*)d_in[14];
    const float* W2         = (const float*)d_in[15];
    const float* b2         = (const float*)d_in[16];
    float* out = (float*)d_out;

    void *pA, *pns, *phin, *ph1, *ph2, *pB, *pR, *pwp1, *pwp2, *pbc1, *pbc2, *pz;
    cudaGetSymbolAddress(&pA, g_bufA);
    cudaGetSymbolAddress(&pB, g_bufB);
    cudaGetSymbolAddress(&pR, g_bufR);
    cudaGetSymbolAddress(&pns, g_norm_src);
    cudaGetSymbolAddress(&phin, g_headin);
    cudaGetSymbolAddress(&ph1, g_head1);
    cudaGetSymbolAddress(&ph2, g_head2);
    cudaGetSymbolAddress(&pwp1, g_wp1);
    cudaGetSymbolAddress(&pwp2, g_wp2);
    cudaGetSymbolAddress(&pbc1, g_bc1);
    cudaGetSymbolAddress(&pbc2, g_bc2);
    cudaGetSymbolAddress(&pz, g_zero);

    const int SMEM_G = (128 * 128 + 64 * 128) * 4;   // 96 KB (head gemm)
    const int SMEM_D = 6 * 128 * LDP * 2;            // 110592 B (dual gemm, bf16 split)
    cudaFuncSetAttribute(k_gemm, cudaFuncAttributeMaxDynamicSharedMemorySize, SMEM_G);
    cudaFuncSetAttribute(k_dualgemm, cudaFuncAttributeMaxDynamicSharedMemorySize, SMEM_D);

    const int gemm_rows = (NN + 127) / 128;   // 391
    const int agg_blocks = (NN + 7) / 8;      // 6250

    // ---- setup ----
    k_zero<<<(NN + 255) / 256, 256>>>();
    k_hist<<<(EE + 255) / 256, 256>>>(src, dst);
    k_norms<<<(NN + 255) / 256, 256>>>();

    // ---- layer-0 dual GEMM (4th launch, ncu-captured): raw weights, b1c=0, b2c=br ----
    k_dualgemm<<<dim3(gemm_rows, 2), 256, SMEM_D>>>(
        node_feats, Wg, Wr, (const float*)pz, br, (const float*)pns,
        (float*)pB, (float*)pR, NN);

    // ---- CSR build (stream-ordered before k_agg) ----
    k_scan1<<<SCAN_B, 256>>>();
    k_scan2<<<1, 256>>>();
    k_scan3<<<SCAN_B, 256>>>();
    k_place<<<(EE + 255) / 256, 256>>>(src, dst);

    for (int l = 0; l < LL; l++) {
        if (l > 0) {
            k_wprep<<<DD, DD>>>(Wg + (size_t)l * DD * DD, Wr + (size_t)l * DD * DD);
            k_wbias<<<1, 2 * DD>>>(Wg + (size_t)l * DD * DD, Wr + (size_t)l * DD * DD,
                                   br + (size_t)l * DD);
            k_dualgemm<<<dim3(gemm_rows, 2), 256, SMEM_D>>>(
                (const float*)pA, (const float*)pwp1, (const float*)pwp2,
                (const float*)pbc1, (const float*)pbc2, (const float*)pns,
                (float*)pB, (float*)pR, NN);
        }

        k_agg<<<agg_blocks, 256>>>(bg + (size_t)l * DD,
                                   (l == 0) ? 1 : 0,
                                   (l == LL - 1) ? 1 : 0,
                                   gid, mid);

        k_bnprep<<<1, DD>>>(gamma + (size_t)l * DD, beta + (size_t)l * DD);
    }

    // ---- finalize: mean pools + layer-2 BN affine ----
    k_finalize<<<((GG + MM) * DD + 255) / 256, 256>>>(out);

    // ---- head MLP on [graph_feats ; h_sub] = 2560 rows ----
    const int HR = GG + MM;
    const int hblocks = (HR + 63) / 64;
    k_gemm<<<dim3(hblocks, FFN / 128), 256, SMEM_G>>>(
        (const float*)phin, W_feat, b_feat, (float*)ph1, HR, DD, FFN, 0);
    k_gemm<<<dim3(hblocks, FFN / 128), 256, SMEM_G>>>(
        (const float*)ph1, W1, b1, (float*)ph2, HR, FFN, FFN, 1);
    k_gemm<<<dim3(hblocks, 1), 256, SMEM_G>>>(
        (const float*)ph2, W2, b2, out + (size_t)GG * DD, HR, FFN, DD, 0);
}